// round 8
// baseline (speedup 1.0000x reference)
#include <cuda_runtime.h>
#include <cuda_bf16.h>
#include <math.h>

// ---------------- problem constants ----------------
#define BB    8
#define FREQ  257
#define TT    1345
#define NF    128
#define NS    64
#define NW    20          // (1345-128-1)/64 + 1
#define WIN   (BB*NW)     // 160
#define C1    8
#define P1H   84
#define P1W   41
#define C2    16
#define P2H   28
#define P2W   14
#define HID   6272        // 16*28*14
#define G3    (3*HID)     // 18816

#define GRU_BLOCKS  112
#define GRU_WARPS   14
#define GRU_THREADS (GRU_WARPS*32)               // 448
#define GRU_SLOTS   (GRU_BLOCKS*GRU_WARPS)       // 1568; 6272 = 4*1568 exactly
#define GRU_SMEM    (4*HID*(int)sizeof(float2))  // 200704 B

// packed fp32x2 FMA: acc = a*b + acc (two full-precision fp32 FMAs, 1 instr)
#define FFMA2ACC(acc, a, b) asm("fma.rn.f32x2 %0, %1, %2, %0;" \
    : "+l"(*(unsigned long long*)&(acc)) \
    : "l"(*(const unsigned long long*)&(a)), "l"(*(const unsigned long long*)&(b)))

// ---------------- device scratch (no allocation allowed) ----------------
__device__ float g_P1[WIN * C1 * P1H * P1W];   // 160*8*84*41
__device__ float g_FEATS[WIN * HID];           // 160*6272
__device__ float g_GI[(size_t)WIN * G3];       // 160*18816
__device__ float g_H[2][BB * HID];             // ping-pong hidden state

// =====================================================================
// K1: conv1 (1->8ch, 9x9, pad2) + maxpool3 + leaky_relu, fused.
// =====================================================================
__global__ void conv1_kernel(const float* __restrict__ x,
                             const float* __restrict__ w,
                             const float* __restrict__ bias)
{
    __shared__ float tile[11][132];
    __shared__ float Ws[C1][9][9];

    const int pr  = blockIdx.x;        // pooled row 0..83
    const int win = blockIdx.y;        // 0..159
    const int b   = win / NW;
    const int wdx = win % NW;
    const int tid = threadIdx.y * 41 + threadIdx.x;   // 0..327

    for (int i = tid; i < C1 * 81; i += 328)
        ((float*)Ws)[i] = w[i];

    const float* xb = x + (size_t)b * FREQ * TT + TT + wdx * NS;
    const int r0 = 3 * pr - 2;
    for (int i = tid; i < 11 * 132; i += 328) {
        int r = i / 132, c = i % 132;
        int gr = r0 + r, gc = c - 2;
        float v = 0.f;
        if (gr >= 0 && gr < 256 && gc >= 0 && gc < NF)
            v = xb[(size_t)gr * TT + gc];
        tile[r][c] = v;
    }
    __syncthreads();

    const int ch = threadIdx.y;
    const int tc = threadIdx.x;
    const float bv = bias[ch];
    float acc[3][3];
#pragma unroll
    for (int i = 0; i < 3; i++)
#pragma unroll
        for (int j = 0; j < 3; j++) acc[i][j] = bv;

#pragma unroll
    for (int r = 0; r < 11; r++) {
        float v[11];
#pragma unroll
        for (int m = 0; m < 11; m++) v[m] = tile[r][3 * tc + m];
#pragma unroll
        for (int i = 0; i < 3; i++) {
            const int kr = r - i;
            if (kr >= 0 && kr <= 8) {
#pragma unroll
                for (int kc = 0; kc < 9; kc++) {
                    float wv = Ws[ch][kr][kc];
                    acc[i][0] = fmaf(wv, v[kc],     acc[i][0]);
                    acc[i][1] = fmaf(wv, v[kc + 1], acc[i][1]);
                    acc[i][2] = fmaf(wv, v[kc + 2], acc[i][2]);
                }
            }
        }
    }
    float m = acc[0][0];
#pragma unroll
    for (int i = 0; i < 3; i++)
#pragma unroll
        for (int j = 0; j < 3; j++) m = fmaxf(m, acc[i][j]);
    float o = (m > 0.f) ? m : 0.01f * m;
    g_P1[(((size_t)win * C1 + ch) * P1H + pr) * P1W + tc] = o;
}

// =====================================================================
// K2: conv2 (8->16ch, 4x4, pad2) + maxpool3 + leaky_relu, fused.
// =====================================================================
__global__ void conv2_kernel(const float* __restrict__ w,
                             const float* __restrict__ bias)
{
    __shared__ float tile[C1][6][46];
    __shared__ float Ws[C2][C1][4][4];

    const int pr  = blockIdx.x;
    const int win = blockIdx.y;
    const int tid = threadIdx.y * 14 + threadIdx.x;   // 0..223

    for (int i = tid; i < C2 * C1 * 16; i += 224)
        ((float*)Ws)[i] = w[i];

    const float* src = g_P1 + (size_t)win * C1 * P1H * P1W;
    const int r0 = 3 * pr - 2;
    for (int i = tid; i < C1 * 6 * 46; i += 224) {
        int ich = i / (6 * 46);
        int rem = i % (6 * 46);
        int r = rem / 46, c = rem % 46;
        int gr = r0 + r, gc = c - 2;
        float v = 0.f;
        if (gr >= 0 && gr < P1H && gc >= 0 && gc < P1W)
            v = src[((size_t)ich * P1H + gr) * P1W + gc];
        tile[ich][r][c] = v;
    }
    __syncthreads();

    const int pc = threadIdx.x;
    const int oc = threadIdx.y;
    const float bv = bias[oc];
    float acc[3][3];
#pragma unroll
    for (int i = 0; i < 3; i++)
#pragma unroll
        for (int j = 0; j < 3; j++) acc[i][j] = bv;

#pragma unroll
    for (int ich = 0; ich < C1; ich++) {
#pragma unroll
        for (int r = 0; r < 6; r++) {
            float v[6];
#pragma unroll
            for (int m = 0; m < 6; m++) v[m] = tile[ich][r][3 * pc + m];
#pragma unroll
            for (int i = 0; i < 3; i++) {
                const int kr = r - i;
                if (kr >= 0 && kr <= 3) {
#pragma unroll
                    for (int kc = 0; kc < 4; kc++) {
                        float wv = Ws[oc][ich][kr][kc];
                        acc[i][0] = fmaf(wv, v[kc],     acc[i][0]);
                        acc[i][1] = fmaf(wv, v[kc + 1], acc[i][1]);
                        acc[i][2] = fmaf(wv, v[kc + 2], acc[i][2]);
                    }
                }
            }
        }
    }
    float m = acc[0][0];
#pragma unroll
    for (int i = 0; i < 3; i++)
#pragma unroll
        for (int j = 0; j < 3; j++) m = fmaxf(m, acc[i][j]);
    float o = (m > 0.f) ? m : 0.01f * m;
    g_FEATS[(size_t)win * HID + oc * (P2H * P2W) + pr * P2W + pc] = o;
}

// =====================================================================
// K3: GI = FEATS(160x6272) @ w_ih^T(6272x18816) + b_ih   (unchanged)
// BM=160, BN=128, BK=16; 256 threads, 10x8 per thread, plain FFMA.
// =====================================================================
__global__ __launch_bounds__(256, 2)
void gi_gemm_kernel(const float* __restrict__ Wih,
                    const float* __restrict__ bih)
{
    __shared__ float As[16][160];
    __shared__ float Bs[16][128];

    const int n0 = blockIdx.x * 128;
    const int tid = threadIdx.x;
    const int ty = tid >> 4;      // 0..15 -> M group (10 rows)
    const int tx = tid & 15;      // 0..15 -> N group (8 cols)

    float acc[10][8];
#pragma unroll
    for (int i = 0; i < 10; i++)
#pragma unroll
        for (int u = 0; u < 8; u++) acc[i][u] = 0.f;

    for (int k0 = 0; k0 < HID; k0 += 16) {
#pragma unroll
        for (int l = 0; l < 10; l++) {
            int idx = tid + l * 256;          // 0..2559
            int m = idx >> 4, kk = idx & 15;
            As[kk][m] = g_FEATS[(size_t)m * HID + k0 + kk];
        }
#pragma unroll
        for (int l = 0; l < 8; l++) {
            int idx = tid + l * 256;          // 0..2047
            int n = idx >> 4, kk = idx & 15;
            Bs[kk][n] = Wih[(size_t)(n0 + n) * HID + k0 + kk];
        }
        __syncthreads();

#pragma unroll
        for (int kk = 0; kk < 16; kk++) {
            float4 b0 = *(const float4*)&Bs[kk][tx * 8];
            float4 b1 = *(const float4*)&Bs[kk][tx * 8 + 4];
            float bb[8] = {b0.x, b0.y, b0.z, b0.w, b1.x, b1.y, b1.z, b1.w};
            float a[10];
#pragma unroll
            for (int i = 0; i < 10; i++) a[i] = As[kk][ty * 10 + i];
#pragma unroll
            for (int i = 0; i < 10; i++)
#pragma unroll
                for (int u = 0; u < 8; u++)
                    acc[i][u] = fmaf(a[i], bb[u], acc[i][u]);
        }
        __syncthreads();
    }

#pragma unroll
    for (int i = 0; i < 10; i++) {
        int m = ty * 10 + i;
#pragma unroll
        for (int u = 0; u < 8; u++) {
            int n = n0 + tx * 8 + u;
            g_GI[(size_t)m * G3 + n] = acc[i][u] + bih[n];
        }
    }
}

// =====================================================================
// K4: one GRU step. grid 112, block 448 (14 warps), h resident in 200KB
// smem as batch-paired float2. 6272 units = 4 per warp exactly
// (2 passes x JU=2). Lane handles k = 2*lane, 2*lane+1 per 64-k chunk:
// h reads are 16B-contiguous LDS.128 (conflict-free), w rows are
// coalesced LDG.64 float2 streams.
// =====================================================================
struct GateAcc { float2 a[4]; };

__device__ __forceinline__ void gru_epilogue(
    int j, int lane, const float2* hp,
    const GateAcc& R, const GateAcc& Z, const GateAcc& N,
    const float* __restrict__ bhh, int t, float* __restrict__ hout)
{
    float rx[4], ry[4], zx[4], zy[4], nx[4], ny[4];
#pragma unroll
    for (int p = 0; p < 4; p++) {
        rx[p] = R.a[p].x; ry[p] = R.a[p].y;
        zx[p] = Z.a[p].x; zy[p] = Z.a[p].y;
        nx[p] = N.a[p].x; ny[p] = N.a[p].y;
#pragma unroll
        for (int off = 16; off > 0; off >>= 1) {
            rx[p] += __shfl_xor_sync(0xffffffffu, rx[p], off);
            ry[p] += __shfl_xor_sync(0xffffffffu, ry[p], off);
            zx[p] += __shfl_xor_sync(0xffffffffu, zx[p], off);
            zy[p] += __shfl_xor_sync(0xffffffffu, zy[p], off);
            nx[p] += __shfl_xor_sync(0xffffffffu, nx[p], off);
            ny[p] += __shfl_xor_sync(0xffffffffu, ny[p], off);
        }
    }
    if (lane < BB) {
        const int b = lane, p = b >> 1;
        const bool hi = b & 1;
        float hr = (hi ? ry[p] : rx[p]) + bhh[j];
        float hz = (hi ? zy[p] : zx[p]) + bhh[j + HID];
        float hn = (hi ? ny[p] : nx[p]) + bhh[j + 2 * HID];
        const float* gib = g_GI + (size_t)(b * NW + t) * G3;
        float r = 1.f / (1.f + expf(-(gib[j] + hr)));
        float z = 1.f / (1.f + expf(-(gib[j + HID] + hz)));
        float n = tanhf(gib[j + 2 * HID] + r * hn);
        float2 hj = hp[p * HID + j];
        float ho = hi ? hj.y : hj.x;
        hout[(size_t)b * HID + j] = (1.f - z) * n + z * ho;
    }
}

__global__ __launch_bounds__(GRU_THREADS, 1)
void gru_step_kernel(const float* __restrict__ Whh,
                     const float* __restrict__ bhh,
                     const float* __restrict__ h0,
                     int t)
{
    extern __shared__ float2 hp[];   // [4][HID]: hp[p][k] = {h[2p][k], h[2p+1][k]}

    const float* hin  = (t == 0) ? h0 : g_H[(t + 1) & 1];
    float*       hout = g_H[t & 1];
    const int tid = threadIdx.x;

    // fill paired h (200KB), coalesced float4 reads
#pragma unroll
    for (int p = 0; p < 4; p++) {
        const float4* r0 = (const float4*)(hin + (size_t)(2 * p) * HID);
        const float4* r1 = (const float4*)(hin + (size_t)(2 * p + 1) * HID);
        for (int q = tid; q < HID / 4; q += GRU_THREADS) {
            float4 a = r0[q], b = r1[q];
            float2* dst = &hp[p * HID + q * 4];
            dst[0] = make_float2(a.x, b.x);
            dst[1] = make_float2(a.y, b.y);
            dst[2] = make_float2(a.z, b.z);
            dst[3] = make_float2(a.w, b.w);
        }
    }
    __syncthreads();

    const int warpId = tid >> 5;
    const int lane   = tid & 31;
    const int slot   = blockIdx.x * GRU_WARPS + warpId;   // 0..1567

#pragma unroll 1
    for (int pass = 0; pass < 2; pass++) {
        const int jA = pass * (2 * GRU_SLOTS) + 2 * slot;   // 0..6270
        const int jB = jA + 1;

        const float2* wrA = (const float2*)(Whh + (size_t)jA * HID);
        const float2* wzA = (const float2*)(Whh + (size_t)(jA + HID) * HID);
        const float2* wnA = (const float2*)(Whh + (size_t)(jA + 2 * HID) * HID);
        const float2* wrB = (const float2*)(Whh + (size_t)jB * HID);
        const float2* wzB = (const float2*)(Whh + (size_t)(jB + HID) * HID);
        const float2* wnB = (const float2*)(Whh + (size_t)(jB + 2 * HID) * HID);

        GateAcc RA, ZA, NA, RB, ZB, NB;
#pragma unroll
        for (int p = 0; p < 4; p++) {
            RA.a[p] = make_float2(0.f, 0.f); ZA.a[p] = make_float2(0.f, 0.f);
            NA.a[p] = make_float2(0.f, 0.f); RB.a[p] = make_float2(0.f, 0.f);
            ZB.a[p] = make_float2(0.f, 0.f); NB.a[p] = make_float2(0.f, 0.f);
        }

#pragma unroll 2
        for (int it = 0; it < HID / 64; it++) {       // 98 iters, 64 k each
            const int q = it * 32 + lane;             // float2 index into w rows
            float2 ra = __ldcs(wrA + q), za = __ldcs(wzA + q), na = __ldcs(wnA + q);
            float2 rb = __ldcs(wrB + q), zb = __ldcs(wzB + q), nb = __ldcs(wnB + q);
            const int k = 2 * q;                      // k, k+1 handled by this lane

            // broadcast packs (hoisted across the 4 batch-pairs)
            float2 rax = make_float2(ra.x, ra.x), ray = make_float2(ra.y, ra.y);
            float2 zax = make_float2(za.x, za.x), zay = make_float2(za.y, za.y);
            float2 nax = make_float2(na.x, na.x), nay = make_float2(na.y, na.y);
            float2 rbx = make_float2(rb.x, rb.x), rby = make_float2(rb.y, rb.y);
            float2 zbx = make_float2(zb.x, zb.x), zby = make_float2(zb.y, zb.y);
            float2 nbx = make_float2(nb.x, nb.x), nby = make_float2(nb.y, nb.y);

#pragma unroll
            for (int p = 0; p < 4; p++) {
                float4 h4 = *(const float4*)(hp + p * HID + k);   // 16B contiguous
                float2 hk  = make_float2(h4.x, h4.y);
                float2 hk1 = make_float2(h4.z, h4.w);
                FFMA2ACC(RA.a[p], rax, hk);  FFMA2ACC(RA.a[p], ray, hk1);
                FFMA2ACC(ZA.a[p], zax, hk);  FFMA2ACC(ZA.a[p], zay, hk1);
                FFMA2ACC(NA.a[p], nax, hk);  FFMA2ACC(NA.a[p], nay, hk1);
                FFMA2ACC(RB.a[p], rbx, hk);  FFMA2ACC(RB.a[p], rby, hk1);
                FFMA2ACC(ZB.a[p], zbx, hk);  FFMA2ACC(ZB.a[p], zby, hk1);
                FFMA2ACC(NB.a[p], nbx, hk);  FFMA2ACC(NB.a[p], nby, hk1);
            }
        }
        gru_epilogue(jA, lane, hp, RA, ZA, NA, bhh, t, hout);
        gru_epilogue(jB, lane, hp, RB, ZB, NB, bhh, t, hout);
    }
}

// =====================================================================
// K5: samples = h @ fc2_w^T + fc2_b ; labels (int32) appended as float32.
// =====================================================================
__global__ void final_fc_kernel(const float* __restrict__ fw,
                                const float* __restrict__ fb,
                                const int* __restrict__ labels,
                                float* __restrict__ out)
{
    const float* h = g_H[(NW - 1) & 1];   // g_H[1]
    const int warpId = threadIdx.x >> 5;
    const int lane   = threadIdx.x & 31;

    for (int p = warpId; p < BB * 10; p += 8) {
        int b = p / 10, c = p % 10;
        const float* hb = h + (size_t)b * HID;
        const float* wc = fw + (size_t)c * HID;
        float s = 0.f;
        for (int k = lane; k < HID; k += 32)
            s = fmaf(hb[k], wc[k], s);
#pragma unroll
        for (int off = 16; off > 0; off >>= 1)
            s += __shfl_xor_sync(0xffffffffu, s, off);
        if (lane == 0)
            out[b * 10 + c] = s + fb[c];
    }
    if (threadIdx.x < BB)
        out[BB * 10 + threadIdx.x] = (float)labels[threadIdx.x];
}

// =====================================================================
extern "C" void kernel_launch(void* const* d_in, const int* in_sizes, int n_in,
                              void* d_out, int out_size)
{
    const float* x       = (const float*)d_in[0];
    const int*   labels  = (const int*)d_in[1];
    const float* h0      = (const float*)d_in[2];
    const float* conv1_w = (const float*)d_in[3];
    const float* conv1_b = (const float*)d_in[4];
    const float* conv2_w = (const float*)d_in[5];
    const float* conv2_b = (const float*)d_in[6];
    const float* w_ih    = (const float*)d_in[7];
    const float* w_hh    = (const float*)d_in[8];
    const float* b_ih    = (const float*)d_in[9];
    const float* b_hh    = (const float*)d_in[10];
    const float* fc2_w   = (const float*)d_in[11];
    const float* fc2_b   = (const float*)d_in[12];
    float*       out     = (float*)d_out;

    cudaFuncSetAttribute(gru_step_kernel,
                         cudaFuncAttributeMaxDynamicSharedMemorySize, GRU_SMEM);

    conv1_kernel<<<dim3(P1H, WIN), dim3(41, 8)>>>(x, conv1_w, conv1_b);
    conv2_kernel<<<dim3(P2H, WIN), dim3(14, 16)>>>(conv2_w, conv2_b);
    gi_gemm_kernel<<<G3 / 128, 256>>>(w_ih, b_ih);
    for (int t = 0; t < NW; t++)
        gru_step_kernel<<<GRU_BLOCKS, GRU_THREADS, GRU_SMEM>>>(w_hh, b_hh, h0, t);
    final_fc_kernel<<<1, 256>>>(fc2_w, fc2_b, labels, out);
}

// round 9
// speedup vs baseline: 1.0004x; 1.0004x over previous
#include <cuda_runtime.h>
#include <cuda_bf16.h>
#include <math.h>

// ---------------- problem constants ----------------
#define BB    8
#define FREQ  257
#define TT    1345
#define NF    128
#define NS    64
#define NW    20          // (1345-128-1)/64 + 1
#define WIN   (BB*NW)     // 160
#define C1    8
#define P1H   84
#define P1W   41
#define C2    16
#define P2H   28
#define P2W   14
#define HID   6272        // 16*28*14
#define G3    (3*HID)     // 18816

#define GRU_BLOCKS  112
#define GRU_WARPS   14
#define GRU_THREADS (GRU_WARPS*32)               // 448
#define GRU_SLOTS   (GRU_BLOCKS*GRU_WARPS)       // 1568; 6272 = 4*1568 exactly
#define GRU_SMEM    (4*HID*(int)sizeof(float2))  // 200704 B

// packed fp32x2 FMA: acc = a*b + acc (two full-precision fp32 FMAs, 1 instr)
#define FFMA2ACC(acc, a, b) asm("fma.rn.f32x2 %0, %1, %2, %0;" \
    : "+l"(*(unsigned long long*)&(acc)) \
    : "l"(*(const unsigned long long*)&(a)), "l"(*(const unsigned long long*)&(b)))

// ---------------- device scratch (no allocation allowed) ----------------
__device__ float g_P1[WIN * C1 * P1H * P1W];   // 160*8*84*41
__device__ float g_FEATS[WIN * HID];           // 160*6272
__device__ float g_GI[(size_t)WIN * G3];       // 160*18816
__device__ float g_H[2][BB * HID];             // ping-pong hidden state

// =====================================================================
// K1: conv1 (1->8ch, 9x9, pad2) + maxpool3 + leaky_relu, fused.
// =====================================================================
__global__ void conv1_kernel(const float* __restrict__ x,
                             const float* __restrict__ w,
                             const float* __restrict__ bias)
{
    __shared__ float tile[11][132];
    __shared__ float Ws[C1][9][9];

    const int pr  = blockIdx.x;        // pooled row 0..83
    const int win = blockIdx.y;        // 0..159
    const int b   = win / NW;
    const int wdx = win % NW;
    const int tid = threadIdx.y * 41 + threadIdx.x;   // 0..327

    for (int i = tid; i < C1 * 81; i += 328)
        ((float*)Ws)[i] = w[i];

    const float* xb = x + (size_t)b * FREQ * TT + TT + wdx * NS;
    const int r0 = 3 * pr - 2;
    for (int i = tid; i < 11 * 132; i += 328) {
        int r = i / 132, c = i % 132;
        int gr = r0 + r, gc = c - 2;
        float v = 0.f;
        if (gr >= 0 && gr < 256 && gc >= 0 && gc < NF)
            v = xb[(size_t)gr * TT + gc];
        tile[r][c] = v;
    }
    __syncthreads();

    const int ch = threadIdx.y;
    const int tc = threadIdx.x;
    const float bv = bias[ch];
    float acc[3][3];
#pragma unroll
    for (int i = 0; i < 3; i++)
#pragma unroll
        for (int j = 0; j < 3; j++) acc[i][j] = bv;

#pragma unroll
    for (int r = 0; r < 11; r++) {
        float v[11];
#pragma unroll
        for (int m = 0; m < 11; m++) v[m] = tile[r][3 * tc + m];
#pragma unroll
        for (int i = 0; i < 3; i++) {
            const int kr = r - i;
            if (kr >= 0 && kr <= 8) {
#pragma unroll
                for (int kc = 0; kc < 9; kc++) {
                    float wv = Ws[ch][kr][kc];
                    acc[i][0] = fmaf(wv, v[kc],     acc[i][0]);
                    acc[i][1] = fmaf(wv, v[kc + 1], acc[i][1]);
                    acc[i][2] = fmaf(wv, v[kc + 2], acc[i][2]);
                }
            }
        }
    }
    float m = acc[0][0];
#pragma unroll
    for (int i = 0; i < 3; i++)
#pragma unroll
        for (int j = 0; j < 3; j++) m = fmaxf(m, acc[i][j]);
    float o = (m > 0.f) ? m : 0.01f * m;
    g_P1[(((size_t)win * C1 + ch) * P1H + pr) * P1W + tc] = o;
}

// =====================================================================
// K2: conv2 (8->16ch, 4x4, pad2) + maxpool3 + leaky_relu, fused.
// =====================================================================
__global__ void conv2_kernel(const float* __restrict__ w,
                             const float* __restrict__ bias)
{
    __shared__ float tile[C1][6][46];
    __shared__ float Ws[C2][C1][4][4];

    const int pr  = blockIdx.x;
    const int win = blockIdx.y;
    const int tid = threadIdx.y * 14 + threadIdx.x;   // 0..223

    for (int i = tid; i < C2 * C1 * 16; i += 224)
        ((float*)Ws)[i] = w[i];

    const float* src = g_P1 + (size_t)win * C1 * P1H * P1W;
    const int r0 = 3 * pr - 2;
    for (int i = tid; i < C1 * 6 * 46; i += 224) {
        int ich = i / (6 * 46);
        int rem = i % (6 * 46);
        int r = rem / 46, c = rem % 46;
        int gr = r0 + r, gc = c - 2;
        float v = 0.f;
        if (gr >= 0 && gr < P1H && gc >= 0 && gc < P1W)
            v = src[((size_t)ich * P1H + gr) * P1W + gc];
        tile[ich][r][c] = v;
    }
    __syncthreads();

    const int pc = threadIdx.x;
    const int oc = threadIdx.y;
    const float bv = bias[oc];
    float acc[3][3];
#pragma unroll
    for (int i = 0; i < 3; i++)
#pragma unroll
        for (int j = 0; j < 3; j++) acc[i][j] = bv;

#pragma unroll
    for (int ich = 0; ich < C1; ich++) {
#pragma unroll
        for (int r = 0; r < 6; r++) {
            float v[6];
#pragma unroll
            for (int m = 0; m < 6; m++) v[m] = tile[ich][r][3 * pc + m];
#pragma unroll
            for (int i = 0; i < 3; i++) {
                const int kr = r - i;
                if (kr >= 0 && kr <= 3) {
#pragma unroll
                    for (int kc = 0; kc < 4; kc++) {
                        float wv = Ws[oc][ich][kr][kc];
                        acc[i][0] = fmaf(wv, v[kc],     acc[i][0]);
                        acc[i][1] = fmaf(wv, v[kc + 1], acc[i][1]);
                        acc[i][2] = fmaf(wv, v[kc + 2], acc[i][2]);
                    }
                }
            }
        }
    }
    float m = acc[0][0];
#pragma unroll
    for (int i = 0; i < 3; i++)
#pragma unroll
        for (int j = 0; j < 3; j++) m = fmaxf(m, acc[i][j]);
    float o = (m > 0.f) ? m : 0.01f * m;
    g_FEATS[(size_t)win * HID + oc * (P2H * P2W) + pr * P2W + pc] = o;
}

// =====================================================================
// K3: GI = FEATS(160x6272) @ w_ih^T(6272x18816) + b_ih   (unchanged)
// BM=160, BN=128, BK=16; 256 threads, 10x8 per thread, plain FFMA.
// =====================================================================
__global__ __launch_bounds__(256, 2)
void gi_gemm_kernel(const float* __restrict__ Wih,
                    const float* __restrict__ bih)
{
    __shared__ float As[16][160];
    __shared__ float Bs[16][128];

    const int n0 = blockIdx.x * 128;
    const int tid = threadIdx.x;
    const int ty = tid >> 4;      // 0..15 -> M group (10 rows)
    const int tx = tid & 15;      // 0..15 -> N group (8 cols)

    float acc[10][8];
#pragma unroll
    for (int i = 0; i < 10; i++)
#pragma unroll
        for (int u = 0; u < 8; u++) acc[i][u] = 0.f;

    for (int k0 = 0; k0 < HID; k0 += 16) {
#pragma unroll
        for (int l = 0; l < 10; l++) {
            int idx = tid + l * 256;          // 0..2559
            int m = idx >> 4, kk = idx & 15;
            As[kk][m] = g_FEATS[(size_t)m * HID + k0 + kk];
        }
#pragma unroll
        for (int l = 0; l < 8; l++) {
            int idx = tid + l * 256;          // 0..2047
            int n = idx >> 4, kk = idx & 15;
            Bs[kk][n] = Wih[(size_t)(n0 + n) * HID + k0 + kk];
        }
        __syncthreads();

#pragma unroll
        for (int kk = 0; kk < 16; kk++) {
            float4 b0 = *(const float4*)&Bs[kk][tx * 8];
            float4 b1 = *(const float4*)&Bs[kk][tx * 8 + 4];
            float bb[8] = {b0.x, b0.y, b0.z, b0.w, b1.x, b1.y, b1.z, b1.w};
            float a[10];
#pragma unroll
            for (int i = 0; i < 10; i++) a[i] = As[kk][ty * 10 + i];
#pragma unroll
            for (int i = 0; i < 10; i++)
#pragma unroll
                for (int u = 0; u < 8; u++)
                    acc[i][u] = fmaf(a[i], bb[u], acc[i][u]);
        }
        __syncthreads();
    }

#pragma unroll
    for (int i = 0; i < 10; i++) {
        int m = ty * 10 + i;
#pragma unroll
        for (int u = 0; u < 8; u++) {
            int n = n0 + tx * 8 + u;
            g_GI[(size_t)m * G3 + n] = acc[i][u] + bih[n];
        }
    }
}

// =====================================================================
// K4: one GRU step. grid 112, block 448 (14 warps), h resident in 200KB
// smem as batch-paired float2. 6272 units = 4 per warp exactly
// (2 passes x JU=2). Lane handles k = 2*lane, 2*lane+1 per 64-k chunk:
// h reads are 16B-contiguous LDS.128 (conflict-free), w rows are
// coalesced LDG.64 float2 streams.
// =====================================================================
struct GateAcc { float2 a[4]; };

__device__ __forceinline__ void gru_epilogue(
    int j, int lane, const float2* hp,
    const GateAcc& R, const GateAcc& Z, const GateAcc& N,
    const float* __restrict__ bhh, int t, float* __restrict__ hout)
{
    float rx[4], ry[4], zx[4], zy[4], nx[4], ny[4];
#pragma unroll
    for (int p = 0; p < 4; p++) {
        rx[p] = R.a[p].x; ry[p] = R.a[p].y;
        zx[p] = Z.a[p].x; zy[p] = Z.a[p].y;
        nx[p] = N.a[p].x; ny[p] = N.a[p].y;
#pragma unroll
        for (int off = 16; off > 0; off >>= 1) {
            rx[p] += __shfl_xor_sync(0xffffffffu, rx[p], off);
            ry[p] += __shfl_xor_sync(0xffffffffu, ry[p], off);
            zx[p] += __shfl_xor_sync(0xffffffffu, zx[p], off);
            zy[p] += __shfl_xor_sync(0xffffffffu, zy[p], off);
            nx[p] += __shfl_xor_sync(0xffffffffu, nx[p], off);
            ny[p] += __shfl_xor_sync(0xffffffffu, ny[p], off);
        }
    }
    if (lane < BB) {
        const int b = lane, p = b >> 1;
        const bool hi = b & 1;
        float hr = (hi ? ry[p] : rx[p]) + bhh[j];
        float hz = (hi ? zy[p] : zx[p]) + bhh[j + HID];
        float hn = (hi ? ny[p] : nx[p]) + bhh[j + 2 * HID];
        const float* gib = g_GI + (size_t)(b * NW + t) * G3;
        float r = 1.f / (1.f + expf(-(gib[j] + hr)));
        float z = 1.f / (1.f + expf(-(gib[j + HID] + hz)));
        float n = tanhf(gib[j + 2 * HID] + r * hn);
        float2 hj = hp[p * HID + j];
        float ho = hi ? hj.y : hj.x;
        hout[(size_t)b * HID + j] = (1.f - z) * n + z * ho;
    }
}

__global__ __launch_bounds__(GRU_THREADS, 1)
void gru_step_kernel(const float* __restrict__ Whh,
                     const float* __restrict__ bhh,
                     const float* __restrict__ h0,
                     int t)
{
    extern __shared__ float2 hp[];   // [4][HID]: hp[p][k] = {h[2p][k], h[2p+1][k]}

    const float* hin  = (t == 0) ? h0 : g_H[(t + 1) & 1];
    float*       hout = g_H[t & 1];
    const int tid = threadIdx.x;

    // fill paired h (200KB), coalesced float4 reads
#pragma unroll
    for (int p = 0; p < 4; p++) {
        const float4* r0 = (const float4*)(hin + (size_t)(2 * p) * HID);
        const float4* r1 = (const float4*)(hin + (size_t)(2 * p + 1) * HID);
        for (int q = tid; q < HID / 4; q += GRU_THREADS) {
            float4 a = r0[q], b = r1[q];
            float2* dst = &hp[p * HID + q * 4];
            dst[0] = make_float2(a.x, b.x);
            dst[1] = make_float2(a.y, b.y);
            dst[2] = make_float2(a.z, b.z);
            dst[3] = make_float2(a.w, b.w);
        }
    }
    __syncthreads();

    const int warpId = tid >> 5;
    const int lane   = tid & 31;
    const int slot   = blockIdx.x * GRU_WARPS + warpId;   // 0..1567

#pragma unroll 1
    for (int pass = 0; pass < 2; pass++) {
        const int jA = pass * (2 * GRU_SLOTS) + 2 * slot;   // 0..6270
        const int jB = jA + 1;

        const float2* wrA = (const float2*)(Whh + (size_t)jA * HID);
        const float2* wzA = (const float2*)(Whh + (size_t)(jA + HID) * HID);
        const float2* wnA = (const float2*)(Whh + (size_t)(jA + 2 * HID) * HID);
        const float2* wrB = (const float2*)(Whh + (size_t)jB * HID);
        const float2* wzB = (const float2*)(Whh + (size_t)(jB + HID) * HID);
        const float2* wnB = (const float2*)(Whh + (size_t)(jB + 2 * HID) * HID);

        GateAcc RA, ZA, NA, RB, ZB, NB;
#pragma unroll
        for (int p = 0; p < 4; p++) {
            RA.a[p] = make_float2(0.f, 0.f); ZA.a[p] = make_float2(0.f, 0.f);
            NA.a[p] = make_float2(0.f, 0.f); RB.a[p] = make_float2(0.f, 0.f);
            ZB.a[p] = make_float2(0.f, 0.f); NB.a[p] = make_float2(0.f, 0.f);
        }

#pragma unroll 2
        for (int it = 0; it < HID / 64; it++) {       // 98 iters, 64 k each
            const int q = it * 32 + lane;             // float2 index into w rows
            float2 ra = __ldcs(wrA + q), za = __ldcs(wzA + q), na = __ldcs(wnA + q);
            float2 rb = __ldcs(wrB + q), zb = __ldcs(wzB + q), nb = __ldcs(wnB + q);
            const int k = 2 * q;                      // k, k+1 handled by this lane

            // broadcast packs (hoisted across the 4 batch-pairs)
            float2 rax = make_float2(ra.x, ra.x), ray = make_float2(ra.y, ra.y);
            float2 zax = make_float2(za.x, za.x), zay = make_float2(za.y, za.y);
            float2 nax = make_float2(na.x, na.x), nay = make_float2(na.y, na.y);
            float2 rbx = make_float2(rb.x, rb.x), rby = make_float2(rb.y, rb.y);
            float2 zbx = make_float2(zb.x, zb.x), zby = make_float2(zb.y, zb.y);
            float2 nbx = make_float2(nb.x, nb.x), nby = make_float2(nb.y, nb.y);

#pragma unroll
            for (int p = 0; p < 4; p++) {
                float4 h4 = *(const float4*)(hp + p * HID + k);   // 16B contiguous
                float2 hk  = make_float2(h4.x, h4.y);
                float2 hk1 = make_float2(h4.z, h4.w);
                FFMA2ACC(RA.a[p], rax, hk);  FFMA2ACC(RA.a[p], ray, hk1);
                FFMA2ACC(ZA.a[p], zax, hk);  FFMA2ACC(ZA.a[p], zay, hk1);
                FFMA2ACC(NA.a[p], nax, hk);  FFMA2ACC(NA.a[p], nay, hk1);
                FFMA2ACC(RB.a[p], rbx, hk);  FFMA2ACC(RB.a[p], rby, hk1);
                FFMA2ACC(ZB.a[p], zbx, hk);  FFMA2ACC(ZB.a[p], zby, hk1);
                FFMA2ACC(NB.a[p], nbx, hk);  FFMA2ACC(NB.a[p], nby, hk1);
            }
        }
        gru_epilogue(jA, lane, hp, RA, ZA, NA, bhh, t, hout);
        gru_epilogue(jB, lane, hp, RB, ZB, NB, bhh, t, hout);
    }
}

// =====================================================================
// K5: samples = h @ fc2_w^T + fc2_b ; labels (int32) appended as float32.
// =====================================================================
__global__ void final_fc_kernel(const float* __restrict__ fw,
                                const float* __restrict__ fb,
                                const int* __restrict__ labels,
                                float* __restrict__ out)
{
    const float* h = g_H[(NW - 1) & 1];   // g_H[1]
    const int warpId = threadIdx.x >> 5;
    const int lane   = threadIdx.x & 31;

    for (int p = warpId; p < BB * 10; p += 8) {
        int b = p / 10, c = p % 10;
        const float* hb = h + (size_t)b * HID;
        const float* wc = fw + (size_t)c * HID;
        float s = 0.f;
        for (int k = lane; k < HID; k += 32)
            s = fmaf(hb[k], wc[k], s);
#pragma unroll
        for (int off = 16; off > 0; off >>= 1)
            s += __shfl_xor_sync(0xffffffffu, s, off);
        if (lane == 0)
            out[b * 10 + c] = s + fb[c];
    }
    if (threadIdx.x < BB)
        out[BB * 10 + threadIdx.x] = (float)labels[threadIdx.x];
}

// =====================================================================
extern "C" void kernel_launch(void* const* d_in, const int* in_sizes, int n_in,
                              void* d_out, int out_size)
{
    const float* x       = (const float*)d_in[0];
    const int*   labels  = (const int*)d_in[1];
    const float* h0      = (const float*)d_in[2];
    const float* conv1_w = (const float*)d_in[3];
    const float* conv1_b = (const float*)d_in[4];
    const float* conv2_w = (const float*)d_in[5];
    const float* conv2_b = (const float*)d_in[6];
    const float* w_ih    = (const float*)d_in[7];
    const float* w_hh    = (const float*)d_in[8];
    const float* b_ih    = (const float*)d_in[9];
    const float* b_hh    = (const float*)d_in[10];
    const float* fc2_w   = (const float*)d_in[11];
    const float* fc2_b   = (const float*)d_in[12];
    float*       out     = (float*)d_out;

    cudaFuncSetAttribute(gru_step_kernel,
                         cudaFuncAttributeMaxDynamicSharedMemorySize, GRU_SMEM);

    conv1_kernel<<<dim3(P1H, WIN), dim3(41, 8)>>>(x, conv1_w, conv1_b);
    conv2_kernel<<<dim3(P2H, WIN), dim3(14, 16)>>>(conv2_w, conv2_b);
    gi_gemm_kernel<<<G3 / 128, 256>>>(w_ih, b_ih);
    for (int t = 0; t < NW; t++)
        gru_step_kernel<<<GRU_BLOCKS, GRU_THREADS, GRU_SMEM>>>(w_hh, b_hh, h0, t);
    final_fc_kernel<<<1, 256>>>(fc2_w, fc2_b, labels, out);
}

// round 10
// speedup vs baseline: 1.0007x; 1.0004x over previous
#include <cuda_runtime.h>
#include <cuda_bf16.h>
#include <math.h>

// ---------------- problem constants ----------------
#define BB    8
#define FREQ  257
#define TT    1345
#define NF    128
#define NS    64
#define NW    20          // (1345-128-1)/64 + 1
#define WIN   (BB*NW)     // 160
#define C1    8
#define P1H   84
#define P1W   41
#define C2    16
#define P2H   28
#define P2W   14
#define HID   6272        // 16*28*14
#define G3    (3*HID)     // 18816

#define GRU_BLOCKS  112
#define GRU_WARPS   14
#define GRU_THREADS (GRU_WARPS*32)               // 448
#define GRU_SLOTS   (GRU_BLOCKS*GRU_WARPS)       // 1568; 6272 = 4*1568 exactly
#define GRU_SMEM    (4*HID*(int)sizeof(float2))  // 200704 B

// packed fp32x2 FMA: acc = a*b + acc (two full-precision fp32 FMAs, 1 instr)
#define FFMA2ACC(acc, a, b) asm("fma.rn.f32x2 %0, %1, %2, %0;" \
    : "+l"(*(unsigned long long*)&(acc)) \
    : "l"(*(const unsigned long long*)&(a)), "l"(*(const unsigned long long*)&(b)))

// ---------------- device scratch (no allocation allowed) ----------------
__device__ float g_P1[WIN * C1 * P1H * P1W];   // 160*8*84*41
__device__ float g_FEATS[WIN * HID];           // 160*6272
__device__ float g_GI[(size_t)WIN * G3];       // 160*18816
__device__ float g_H[2][BB * HID];             // ping-pong hidden state

// =====================================================================
// K1: conv1 (1->8ch, 9x9, pad2) + maxpool3 + leaky_relu, fused.
// =====================================================================
__global__ void conv1_kernel(const float* __restrict__ x,
                             const float* __restrict__ w,
                             const float* __restrict__ bias)
{
    __shared__ float tile[11][132];
    __shared__ float Ws[C1][9][9];

    const int pr  = blockIdx.x;        // pooled row 0..83
    const int win = blockIdx.y;        // 0..159
    const int b   = win / NW;
    const int wdx = win % NW;
    const int tid = threadIdx.y * 41 + threadIdx.x;   // 0..327

    for (int i = tid; i < C1 * 81; i += 328)
        ((float*)Ws)[i] = w[i];

    const float* xb = x + (size_t)b * FREQ * TT + TT + wdx * NS;
    const int r0 = 3 * pr - 2;
    for (int i = tid; i < 11 * 132; i += 328) {
        int r = i / 132, c = i % 132;
        int gr = r0 + r, gc = c - 2;
        float v = 0.f;
        if (gr >= 0 && gr < 256 && gc >= 0 && gc < NF)
            v = xb[(size_t)gr * TT + gc];
        tile[r][c] = v;
    }
    __syncthreads();

    const int ch = threadIdx.y;
    const int tc = threadIdx.x;
    const float bv = bias[ch];
    float acc[3][3];
#pragma unroll
    for (int i = 0; i < 3; i++)
#pragma unroll
        for (int j = 0; j < 3; j++) acc[i][j] = bv;

#pragma unroll
    for (int r = 0; r < 11; r++) {
        float v[11];
#pragma unroll
        for (int m = 0; m < 11; m++) v[m] = tile[r][3 * tc + m];
#pragma unroll
        for (int i = 0; i < 3; i++) {
            const int kr = r - i;
            if (kr >= 0 && kr <= 8) {
#pragma unroll
                for (int kc = 0; kc < 9; kc++) {
                    float wv = Ws[ch][kr][kc];
                    acc[i][0] = fmaf(wv, v[kc],     acc[i][0]);
                    acc[i][1] = fmaf(wv, v[kc + 1], acc[i][1]);
                    acc[i][2] = fmaf(wv, v[kc + 2], acc[i][2]);
                }
            }
        }
    }
    float m = acc[0][0];
#pragma unroll
    for (int i = 0; i < 3; i++)
#pragma unroll
        for (int j = 0; j < 3; j++) m = fmaxf(m, acc[i][j]);
    float o = (m > 0.f) ? m : 0.01f * m;
    g_P1[(((size_t)win * C1 + ch) * P1H + pr) * P1W + tc] = o;
}

// =====================================================================
// K2: conv2 (8->16ch, 4x4, pad2) + maxpool3 + leaky_relu, fused.
// =====================================================================
__global__ void conv2_kernel(const float* __restrict__ w,
                             const float* __restrict__ bias)
{
    __shared__ float tile[C1][6][46];
    __shared__ float Ws[C2][C1][4][4];

    const int pr  = blockIdx.x;
    const int win = blockIdx.y;
    const int tid = threadIdx.y * 14 + threadIdx.x;   // 0..223

    for (int i = tid; i < C2 * C1 * 16; i += 224)
        ((float*)Ws)[i] = w[i];

    const float* src = g_P1 + (size_t)win * C1 * P1H * P1W;
    const int r0 = 3 * pr - 2;
    for (int i = tid; i < C1 * 6 * 46; i += 224) {
        int ich = i / (6 * 46);
        int rem = i % (6 * 46);
        int r = rem / 46, c = rem % 46;
        int gr = r0 + r, gc = c - 2;
        float v = 0.f;
        if (gr >= 0 && gr < P1H && gc >= 0 && gc < P1W)
            v = src[((size_t)ich * P1H + gr) * P1W + gc];
        tile[ich][r][c] = v;
    }
    __syncthreads();

    const int pc = threadIdx.x;
    const int oc = threadIdx.y;
    const float bv = bias[oc];
    float acc[3][3];
#pragma unroll
    for (int i = 0; i < 3; i++)
#pragma unroll
        for (int j = 0; j < 3; j++) acc[i][j] = bv;

#pragma unroll
    for (int ich = 0; ich < C1; ich++) {
#pragma unroll
        for (int r = 0; r < 6; r++) {
            float v[6];
#pragma unroll
            for (int m = 0; m < 6; m++) v[m] = tile[ich][r][3 * pc + m];
#pragma unroll
            for (int i = 0; i < 3; i++) {
                const int kr = r - i;
                if (kr >= 0 && kr <= 3) {
#pragma unroll
                    for (int kc = 0; kc < 4; kc++) {
                        float wv = Ws[oc][ich][kr][kc];
                        acc[i][0] = fmaf(wv, v[kc],     acc[i][0]);
                        acc[i][1] = fmaf(wv, v[kc + 1], acc[i][1]);
                        acc[i][2] = fmaf(wv, v[kc + 2], acc[i][2]);
                    }
                }
            }
        }
    }
    float m = acc[0][0];
#pragma unroll
    for (int i = 0; i < 3; i++)
#pragma unroll
        for (int j = 0; j < 3; j++) m = fmaxf(m, acc[i][j]);
    float o = (m > 0.f) ? m : 0.01f * m;
    g_FEATS[(size_t)win * HID + oc * (P2H * P2W) + pr * P2W + pc] = o;
}

// =====================================================================
// K3: GI = FEATS(160x6272) @ w_ih^T(6272x18816) + b_ih   (unchanged)
// BM=160, BN=128, BK=16; 256 threads, 10x8 per thread, plain FFMA.
// =====================================================================
__global__ __launch_bounds__(256, 2)
void gi_gemm_kernel(const float* __restrict__ Wih,
                    const float* __restrict__ bih)
{
    __shared__ float As[16][160];
    __shared__ float Bs[16][128];

    const int n0 = blockIdx.x * 128;
    const int tid = threadIdx.x;
    const int ty = tid >> 4;      // 0..15 -> M group (10 rows)
    const int tx = tid & 15;      // 0..15 -> N group (8 cols)

    float acc[10][8];
#pragma unroll
    for (int i = 0; i < 10; i++)
#pragma unroll
        for (int u = 0; u < 8; u++) acc[i][u] = 0.f;

    for (int k0 = 0; k0 < HID; k0 += 16) {
#pragma unroll
        for (int l = 0; l < 10; l++) {
            int idx = tid + l * 256;          // 0..2559
            int m = idx >> 4, kk = idx & 15;
            As[kk][m] = g_FEATS[(size_t)m * HID + k0 + kk];
        }
#pragma unroll
        for (int l = 0; l < 8; l++) {
            int idx = tid + l * 256;          // 0..2047
            int n = idx >> 4, kk = idx & 15;
            Bs[kk][n] = Wih[(size_t)(n0 + n) * HID + k0 + kk];
        }
        __syncthreads();

#pragma unroll
        for (int kk = 0; kk < 16; kk++) {
            float4 b0 = *(const float4*)&Bs[kk][tx * 8];
            float4 b1 = *(const float4*)&Bs[kk][tx * 8 + 4];
            float bb[8] = {b0.x, b0.y, b0.z, b0.w, b1.x, b1.y, b1.z, b1.w};
            float a[10];
#pragma unroll
            for (int i = 0; i < 10; i++) a[i] = As[kk][ty * 10 + i];
#pragma unroll
            for (int i = 0; i < 10; i++)
#pragma unroll
                for (int u = 0; u < 8; u++)
                    acc[i][u] = fmaf(a[i], bb[u], acc[i][u]);
        }
        __syncthreads();
    }

#pragma unroll
    for (int i = 0; i < 10; i++) {
        int m = ty * 10 + i;
#pragma unroll
        for (int u = 0; u < 8; u++) {
            int n = n0 + tx * 8 + u;
            g_GI[(size_t)m * G3 + n] = acc[i][u] + bih[n];
        }
    }
}

// =====================================================================
// K4: one GRU step. grid 112, block 448 (14 warps), h resident in 200KB
// smem as batch-paired float2. 6272 units = 4 per warp exactly
// (2 passes x JU=2). Lane handles k = 2*lane, 2*lane+1 per 64-k chunk:
// h reads are 16B-contiguous LDS.128 (conflict-free), w rows are
// coalesced LDG.64 float2 streams.
// =====================================================================
struct GateAcc { float2 a[4]; };

__device__ __forceinline__ void gru_epilogue(
    int j, int lane, const float2* hp,
    const GateAcc& R, const GateAcc& Z, const GateAcc& N,
    const float* __restrict__ bhh, int t, float* __restrict__ hout)
{
    float rx[4], ry[4], zx[4], zy[4], nx[4], ny[4];
#pragma unroll
    for (int p = 0; p < 4; p++) {
        rx[p] = R.a[p].x; ry[p] = R.a[p].y;
        zx[p] = Z.a[p].x; zy[p] = Z.a[p].y;
        nx[p] = N.a[p].x; ny[p] = N.a[p].y;
#pragma unroll
        for (int off = 16; off > 0; off >>= 1) {
            rx[p] += __shfl_xor_sync(0xffffffffu, rx[p], off);
            ry[p] += __shfl_xor_sync(0xffffffffu, ry[p], off);
            zx[p] += __shfl_xor_sync(0xffffffffu, zx[p], off);
            zy[p] += __shfl_xor_sync(0xffffffffu, zy[p], off);
            nx[p] += __shfl_xor_sync(0xffffffffu, nx[p], off);
            ny[p] += __shfl_xor_sync(0xffffffffu, ny[p], off);
        }
    }
    if (lane < BB) {
        const int b = lane, p = b >> 1;
        const bool hi = b & 1;
        float hr = (hi ? ry[p] : rx[p]) + bhh[j];
        float hz = (hi ? zy[p] : zx[p]) + bhh[j + HID];
        float hn = (hi ? ny[p] : nx[p]) + bhh[j + 2 * HID];
        const float* gib = g_GI + (size_t)(b * NW + t) * G3;
        float r = 1.f / (1.f + expf(-(gib[j] + hr)));
        float z = 1.f / (1.f + expf(-(gib[j + HID] + hz)));
        float n = tanhf(gib[j + 2 * HID] + r * hn);
        float2 hj = hp[p * HID + j];
        float ho = hi ? hj.y : hj.x;
        hout[(size_t)b * HID + j] = (1.f - z) * n + z * ho;
    }
}

__global__ __launch_bounds__(GRU_THREADS, 1)
void gru_step_kernel(const float* __restrict__ Whh,
                     const float* __restrict__ bhh,
                     const float* __restrict__ h0,
                     int t)
{
    extern __shared__ float2 hp[];   // [4][HID]: hp[p][k] = {h[2p][k], h[2p+1][k]}

    const float* hin  = (t == 0) ? h0 : g_H[(t + 1) & 1];
    float*       hout = g_H[t & 1];
    const int tid = threadIdx.x;

    // fill paired h (200KB), coalesced float4 reads
#pragma unroll
    for (int p = 0; p < 4; p++) {
        const float4* r0 = (const float4*)(hin + (size_t)(2 * p) * HID);
        const float4* r1 = (const float4*)(hin + (size_t)(2 * p + 1) * HID);
        for (int q = tid; q < HID / 4; q += GRU_THREADS) {
            float4 a = r0[q], b = r1[q];
            float2* dst = &hp[p * HID + q * 4];
            dst[0] = make_float2(a.x, b.x);
            dst[1] = make_float2(a.y, b.y);
            dst[2] = make_float2(a.z, b.z);
            dst[3] = make_float2(a.w, b.w);
        }
    }
    __syncthreads();

    const int warpId = tid >> 5;
    const int lane   = tid & 31;
    const int slot   = blockIdx.x * GRU_WARPS + warpId;   // 0..1567

#pragma unroll 1
    for (int pass = 0; pass < 2; pass++) {
        const int jA = pass * (2 * GRU_SLOTS) + 2 * slot;   // 0..6270
        const int jB = jA + 1;

        const float2* wrA = (const float2*)(Whh + (size_t)jA * HID);
        const float2* wzA = (const float2*)(Whh + (size_t)(jA + HID) * HID);
        const float2* wnA = (const float2*)(Whh + (size_t)(jA + 2 * HID) * HID);
        const float2* wrB = (const float2*)(Whh + (size_t)jB * HID);
        const float2* wzB = (const float2*)(Whh + (size_t)(jB + HID) * HID);
        const float2* wnB = (const float2*)(Whh + (size_t)(jB + 2 * HID) * HID);

        GateAcc RA, ZA, NA, RB, ZB, NB;
#pragma unroll
        for (int p = 0; p < 4; p++) {
            RA.a[p] = make_float2(0.f, 0.f); ZA.a[p] = make_float2(0.f, 0.f);
            NA.a[p] = make_float2(0.f, 0.f); RB.a[p] = make_float2(0.f, 0.f);
            ZB.a[p] = make_float2(0.f, 0.f); NB.a[p] = make_float2(0.f, 0.f);
        }

#pragma unroll 2
        for (int it = 0; it < HID / 64; it++) {       // 98 iters, 64 k each
            const int q = it * 32 + lane;             // float2 index into w rows
            float2 ra = __ldcs(wrA + q), za = __ldcs(wzA + q), na = __ldcs(wnA + q);
            float2 rb = __ldcs(wrB + q), zb = __ldcs(wzB + q), nb = __ldcs(wnB + q);
            const int k = 2 * q;                      // k, k+1 handled by this lane

            // broadcast packs (hoisted across the 4 batch-pairs)
            float2 rax = make_float2(ra.x, ra.x), ray = make_float2(ra.y, ra.y);
            float2 zax = make_float2(za.x, za.x), zay = make_float2(za.y, za.y);
            float2 nax = make_float2(na.x, na.x), nay = make_float2(na.y, na.y);
            float2 rbx = make_float2(rb.x, rb.x), rby = make_float2(rb.y, rb.y);
            float2 zbx = make_float2(zb.x, zb.x), zby = make_float2(zb.y, zb.y);
            float2 nbx = make_float2(nb.x, nb.x), nby = make_float2(nb.y, nb.y);

#pragma unroll
            for (int p = 0; p < 4; p++) {
                float4 h4 = *(const float4*)(hp + p * HID + k);   // 16B contiguous
                float2 hk  = make_float2(h4.x, h4.y);
                float2 hk1 = make_float2(h4.z, h4.w);
                FFMA2ACC(RA.a[p], rax, hk);  FFMA2ACC(RA.a[p], ray, hk1);
                FFMA2ACC(ZA.a[p], zax, hk);  FFMA2ACC(ZA.a[p], zay, hk1);
                FFMA2ACC(NA.a[p], nax, hk);  FFMA2ACC(NA.a[p], nay, hk1);
                FFMA2ACC(RB.a[p], rbx, hk);  FFMA2ACC(RB.a[p], rby, hk1);
                FFMA2ACC(ZB.a[p], zbx, hk);  FFMA2ACC(ZB.a[p], zby, hk1);
                FFMA2ACC(NB.a[p], nbx, hk);  FFMA2ACC(NB.a[p], nby, hk1);
            }
        }
        gru_epilogue(jA, lane, hp, RA, ZA, NA, bhh, t, hout);
        gru_epilogue(jB, lane, hp, RB, ZB, NB, bhh, t, hout);
    }
}

// =====================================================================
// K5: samples = h @ fc2_w^T + fc2_b ; labels (int32) appended as float32.
// =====================================================================
__global__ void final_fc_kernel(const float* __restrict__ fw,
                                const float* __restrict__ fb,
                                const int* __restrict__ labels,
                                float* __restrict__ out)
{
    const float* h = g_H[(NW - 1) & 1];   // g_H[1]
    const int warpId = threadIdx.x >> 5;
    const int lane   = threadIdx.x & 31;

    for (int p = warpId; p < BB * 10; p += 8) {
        int b = p / 10, c = p % 10;
        const float* hb = h + (size_t)b * HID;
        const float* wc = fw + (size_t)c * HID;
        float s = 0.f;
        for (int k = lane; k < HID; k += 32)
            s = fmaf(hb[k], wc[k], s);
#pragma unroll
        for (int off = 16; off > 0; off >>= 1)
            s += __shfl_xor_sync(0xffffffffu, s, off);
        if (lane == 0)
            out[b * 10 + c] = s + fb[c];
    }
    if (threadIdx.x < BB)
        out[BB * 10 + threadIdx.x] = (float)labels[threadIdx.x];
}

// =====================================================================
extern "C" void kernel_launch(void* const* d_in, const int* in_sizes, int n_in,
                              void* d_out, int out_size)
{
    const float* x       = (const float*)d_in[0];
    const int*   labels  = (const int*)d_in[1];
    const float* h0      = (const float*)d_in[2];
    const float* conv1_w = (const float*)d_in[3];
    const float* conv1_b = (const float*)d_in[4];
    const float* conv2_w = (const float*)d_in[5];
    const float* conv2_b = (const float*)d_in[6];
    const float* w_ih    = (const float*)d_in[7];
    const float* w_hh    = (const float*)d_in[8];
    const float* b_ih    = (const float*)d_in[9];
    const float* b_hh    = (const float*)d_in[10];
    const float* fc2_w   = (const float*)d_in[11];
    const float* fc2_b   = (const float*)d_in[12];
    float*       out     = (float*)d_out;

    cudaFuncSetAttribute(gru_step_kernel,
                         cudaFuncAttributeMaxDynamicSharedMemorySize, GRU_SMEM);

    conv1_kernel<<<dim3(P1H, WIN), dim3(41, 8)>>>(x, conv1_w, conv1_b);
    conv2_kernel<<<dim3(P2H, WIN), dim3(14, 16)>>>(conv2_w, conv2_b);
    gi_gemm_kernel<<<G3 / 128, 256>>>(w_ih, b_ih);
    for (int t = 0; t < NW; t++)
        gru_step_kernel<<<GRU_BLOCKS, GRU_THREADS, GRU_SMEM>>>(w_hh, b_hh, h0, t);
    final_fc_kernel<<<1, 256>>>(fc2_w, fc2_b, labels, out);
}

// round 11
// speedup vs baseline: 1.1043x; 1.1035x over previous
#include <cuda_runtime.h>
#include <cuda_bf16.h>
#include <math.h>

// ---------------- problem constants ----------------
#define BB    8
#define FREQ  257
#define TT    1345
#define NF    128
#define NS    64
#define NW    20          // (1345-128-1)/64 + 1
#define WIN   (BB*NW)     // 160
#define C1    8
#define P1H   84
#define P1W   41
#define C2    16
#define P2H   28
#define P2W   14
#define HID   6272        // 16*28*14
#define G3    (3*HID)     // 18816
#define HID2  (HID/2)     // 3136 float2 per row
#define HID4  (HID/4)     // 1568 uint2 (bf16x4) per row

#define GRU_BLOCKS  148
#define GRU_WARPS   14
#define GRU_THREADS (GRU_WARPS*32)               // 448
#define GRU_SLOTS   (GRU_BLOCKS*GRU_WARPS)       // 2072
#define GRU_SMEM    (4*HID2*(int)sizeof(float4)) // 200704 B
// coverage: JU2 pass = 4144 units, JU1 pass = 2072, tail 56 -> 6272 exactly
#define P1_UNITS    (2*GRU_SLOTS)                // 4144
#define P2_BASE     P1_UNITS                     // 4144
#define P3_BASE     (P1_UNITS + GRU_SLOTS)       // 6216
#define P3_COUNT    (HID - P3_BASE)              // 56

// packed fp32x2 FMA: acc = a*b + acc (two full-precision fp32 FMAs, 1 instr)
#define FFMA2ACC(acc, a, b) asm("fma.rn.f32x2 %0, %1, %2, %0;" \
    : "+l"(*(unsigned long long*)&(acc)) \
    : "l"(*(const unsigned long long*)&(a)), "l"(*(const unsigned long long*)&(b)))

// ---------------- device scratch (no allocation allowed) ----------------
__device__ float g_P1[WIN * C1 * P1H * P1W];   // 160*8*84*41
__device__ float g_FEATS[WIN * HID];           // 160*6272
__device__ float g_GI[(size_t)WIN * G3];       // 160*18816
__device__ float g_H[2][BB * HID];             // ping-pong hidden state
__device__ uint2 g_WBF[(size_t)G3 * HID4];     // w_hh in bf16 (236 MB)

// =====================================================================
// K0: convert w_hh fp32 -> bf16 (row-major, rn rounding)
// =====================================================================
__global__ void whh_to_bf16_kernel(const float* __restrict__ w)
{
    const size_t n4 = (size_t)G3 * HID4;       // uint2 count = float4 count
    const float4* src = (const float4*)w;
    for (size_t i = (size_t)blockIdx.x * blockDim.x + threadIdx.x;
         i < n4; i += (size_t)gridDim.x * blockDim.x) {
        float4 v = src[i];
        __nv_bfloat162 lo = __floats2bfloat162_rn(v.x, v.y);
        __nv_bfloat162 hi = __floats2bfloat162_rn(v.z, v.w);
        uint2 o;
        o.x = *(unsigned*)&lo;
        o.y = *(unsigned*)&hi;
        g_WBF[i] = o;
    }
}

// =====================================================================
// K1: conv1 (1->8ch, 9x9, pad2) + maxpool3 + leaky_relu, fused.
// =====================================================================
__global__ void conv1_kernel(const float* __restrict__ x,
                             const float* __restrict__ w,
                             const float* __restrict__ bias)
{
    __shared__ float tile[11][132];
    __shared__ float Ws[C1][9][9];

    const int pr  = blockIdx.x;
    const int win = blockIdx.y;
    const int b   = win / NW;
    const int wdx = win % NW;
    const int tid = threadIdx.y * 41 + threadIdx.x;

    for (int i = tid; i < C1 * 81; i += 328)
        ((float*)Ws)[i] = w[i];

    const float* xb = x + (size_t)b * FREQ * TT + TT + wdx * NS;
    const int r0 = 3 * pr - 2;
    for (int i = tid; i < 11 * 132; i += 328) {
        int r = i / 132, c = i % 132;
        int gr = r0 + r, gc = c - 2;
        float v = 0.f;
        if (gr >= 0 && gr < 256 && gc >= 0 && gc < NF)
            v = xb[(size_t)gr * TT + gc];
        tile[r][c] = v;
    }
    __syncthreads();

    const int ch = threadIdx.y;
    const int tc = threadIdx.x;
    const float bv = bias[ch];
    float acc[3][3];
#pragma unroll
    for (int i = 0; i < 3; i++)
#pragma unroll
        for (int j = 0; j < 3; j++) acc[i][j] = bv;

#pragma unroll
    for (int r = 0; r < 11; r++) {
        float v[11];
#pragma unroll
        for (int m = 0; m < 11; m++) v[m] = tile[r][3 * tc + m];
#pragma unroll
        for (int i = 0; i < 3; i++) {
            const int kr = r - i;
            if (kr >= 0 && kr <= 8) {
#pragma unroll
                for (int kc = 0; kc < 9; kc++) {
                    float wv = Ws[ch][kr][kc];
                    acc[i][0] = fmaf(wv, v[kc],     acc[i][0]);
                    acc[i][1] = fmaf(wv, v[kc + 1], acc[i][1]);
                    acc[i][2] = fmaf(wv, v[kc + 2], acc[i][2]);
                }
            }
        }
    }
    float m = acc[0][0];
#pragma unroll
    for (int i = 0; i < 3; i++)
#pragma unroll
        for (int j = 0; j < 3; j++) m = fmaxf(m, acc[i][j]);
    float o = (m > 0.f) ? m : 0.01f * m;
    g_P1[(((size_t)win * C1 + ch) * P1H + pr) * P1W + tc] = o;
}

// =====================================================================
// K2: conv2 (8->16ch, 4x4, pad2) + maxpool3 + leaky_relu, fused.
// =====================================================================
__global__ void conv2_kernel(const float* __restrict__ w,
                             const float* __restrict__ bias)
{
    __shared__ float tile[C1][6][46];
    __shared__ float Ws[C2][C1][4][4];

    const int pr  = blockIdx.x;
    const int win = blockIdx.y;
    const int tid = threadIdx.y * 14 + threadIdx.x;

    for (int i = tid; i < C2 * C1 * 16; i += 224)
        ((float*)Ws)[i] = w[i];

    const float* src = g_P1 + (size_t)win * C1 * P1H * P1W;
    const int r0 = 3 * pr - 2;
    for (int i = tid; i < C1 * 6 * 46; i += 224) {
        int ich = i / (6 * 46);
        int rem = i % (6 * 46);
        int r = rem / 46, c = rem % 46;
        int gr = r0 + r, gc = c - 2;
        float v = 0.f;
        if (gr >= 0 && gr < P1H && gc >= 0 && gc < P1W)
            v = src[((size_t)ich * P1H + gr) * P1W + gc];
        tile[ich][r][c] = v;
    }
    __syncthreads();

    const int pc = threadIdx.x;
    const int oc = threadIdx.y;
    const float bv = bias[oc];
    float acc[3][3];
#pragma unroll
    for (int i = 0; i < 3; i++)
#pragma unroll
        for (int j = 0; j < 3; j++) acc[i][j] = bv;

#pragma unroll
    for (int ich = 0; ich < C1; ich++) {
#pragma unroll
        for (int r = 0; r < 6; r++) {
            float v[6];
#pragma unroll
            for (int m = 0; m < 6; m++) v[m] = tile[ich][r][3 * pc + m];
#pragma unroll
            for (int i = 0; i < 3; i++) {
                const int kr = r - i;
                if (kr >= 0 && kr <= 3) {
#pragma unroll
                    for (int kc = 0; kc < 4; kc++) {
                        float wv = Ws[oc][ich][kr][kc];
                        acc[i][0] = fmaf(wv, v[kc],     acc[i][0]);
                        acc[i][1] = fmaf(wv, v[kc + 1], acc[i][1]);
                        acc[i][2] = fmaf(wv, v[kc + 2], acc[i][2]);
                    }
                }
            }
        }
    }
    float m = acc[0][0];
#pragma unroll
    for (int i = 0; i < 3; i++)
#pragma unroll
        for (int j = 0; j < 3; j++) m = fmaxf(m, acc[i][j]);
    float o = (m > 0.f) ? m : 0.01f * m;
    g_FEATS[(size_t)win * HID + oc * (P2H * P2W) + pr * P2W + pc] = o;
}

// =====================================================================
// K3: GI = FEATS(160x6272) @ w_ih^T(6272x18816) + b_ih   (R4/R6 version)
// =====================================================================
__global__ __launch_bounds__(256, 2)
void gi_gemm_kernel(const float* __restrict__ Wih,
                    const float* __restrict__ bih)
{
    __shared__ float As[16][160];
    __shared__ float Bs[16][128];

    const int n0 = blockIdx.x * 128;
    const int tid = threadIdx.x;
    const int ty = tid >> 4;
    const int tx = tid & 15;

    float acc[10][8];
#pragma unroll
    for (int i = 0; i < 10; i++)
#pragma unroll
        for (int u = 0; u < 8; u++) acc[i][u] = 0.f;

    for (int k0 = 0; k0 < HID; k0 += 16) {
#pragma unroll
        for (int l = 0; l < 10; l++) {
            int idx = tid + l * 256;
            int m = idx >> 4, kk = idx & 15;
            As[kk][m] = g_FEATS[(size_t)m * HID + k0 + kk];
        }
#pragma unroll
        for (int l = 0; l < 8; l++) {
            int idx = tid + l * 256;
            int n = idx >> 4, kk = idx & 15;
            Bs[kk][n] = Wih[(size_t)(n0 + n) * HID + k0 + kk];
        }
        __syncthreads();

#pragma unroll
        for (int kk = 0; kk < 16; kk++) {
            float4 b0 = *(const float4*)&Bs[kk][tx * 8];
            float4 b1 = *(const float4*)&Bs[kk][tx * 8 + 4];
            float bb[8] = {b0.x, b0.y, b0.z, b0.w, b1.x, b1.y, b1.z, b1.w};
            float a[10];
#pragma unroll
            for (int i = 0; i < 10; i++) a[i] = As[kk][ty * 10 + i];
#pragma unroll
            for (int i = 0; i < 10; i++)
#pragma unroll
                for (int u = 0; u < 8; u++)
                    acc[i][u] = fmaf(a[i], bb[u], acc[i][u]);
        }
        __syncthreads();
    }

#pragma unroll
    for (int i = 0; i < 10; i++) {
        int m = ty * 10 + i;
#pragma unroll
        for (int u = 0; u < 8; u++) {
            int n = n0 + tx * 8 + u;
            g_GI[(size_t)m * G3 + n] = acc[i][u] + bih[n];
        }
    }
}

// =====================================================================
// K4: GRU step with bf16 w_hh. 148 blocks x 448 thr. h resident in 200KB
// smem as swizzled batch-paired float4 units: unit U = p*HID2 + m holds
// (h[2p][2m], h[2p+1][2m], h[2p][2m+1], h[2p+1][2m+1]) at slot U^((U>>3)&1)
// (bank-conflict-free for the stride-2-unit read pattern).
// =====================================================================
__device__ __forceinline__ int swz(int u) { return u ^ ((u >> 3) & 1); }

// reduce + gate math + store for one unit j given acc[3][4] (r,z,n gates)
__device__ __forceinline__ void gru_epilogue(
    int j, int lane, const float4* hp4,
    float2 aR[4], float2 aZ[4], float2 aN[4],
    const float* __restrict__ bhh, int t, float* __restrict__ hout)
{
    float rx[4], ry[4], zx[4], zy[4], nx[4], ny[4];
#pragma unroll
    for (int p = 0; p < 4; p++) {
        rx[p] = aR[p].x; ry[p] = aR[p].y;
        zx[p] = aZ[p].x; zy[p] = aZ[p].y;
        nx[p] = aN[p].x; ny[p] = aN[p].y;
#pragma unroll
        for (int off = 16; off > 0; off >>= 1) {
            rx[p] += __shfl_xor_sync(0xffffffffu, rx[p], off);
            ry[p] += __shfl_xor_sync(0xffffffffu, ry[p], off);
            zx[p] += __shfl_xor_sync(0xffffffffu, zx[p], off);
            zy[p] += __shfl_xor_sync(0xffffffffu, zy[p], off);
            nx[p] += __shfl_xor_sync(0xffffffffu, nx[p], off);
            ny[p] += __shfl_xor_sync(0xffffffffu, ny[p], off);
        }
    }
    if (lane < BB) {
        const int b = lane, p = b >> 1;
        const bool hi = b & 1;
        float hr = (hi ? ry[p] : rx[p]) + bhh[j];
        float hz = (hi ? zy[p] : zx[p]) + bhh[j + HID];
        float hn = (hi ? ny[p] : nx[p]) + bhh[j + 2 * HID];
        const float* gib = g_GI + (size_t)(b * NW + t) * G3;
        float r = 1.f / (1.f + expf(-(gib[j] + hr)));
        float z = 1.f / (1.f + expf(-(gib[j + HID] + hz)));
        float n = tanhf(gib[j + 2 * HID] + r * hn);
        // h_old from swizzled smem
        int U = p * HID2 + (j >> 1);
        const float2* h2 = (const float2*)hp4;
        float2 hpair = h2[2 * swz(U) + (j & 1)];
        float ho = hi ? hpair.y : hpair.x;
        hout[(size_t)b * HID + j] = (1.f - z) * n + z * ho;
    }
}

// stream 2 adjacent units jA, jA+1 (6 bf16 rows)
__device__ __forceinline__ void gru_stream2(
    int jA, int lane, const float4* hp4,
    const float* __restrict__ bhh, int t, float* __restrict__ hout)
{
    const uint2* r0 = g_WBF + (size_t)jA * HID4;            // rA
    const uint2* r1 = g_WBF + (size_t)(jA + HID) * HID4;    // zA
    const uint2* r2 = g_WBF + (size_t)(jA + 2*HID) * HID4;  // nA
    const uint2* r3 = r0 + HID4;                            // rB (row jA+1)
    const uint2* r4 = r1 + HID4;                            // zB
    const uint2* r5 = r2 + HID4;                            // nB

    float2 acc[6][4];
#pragma unroll
    for (int s = 0; s < 6; s++)
#pragma unroll
        for (int p = 0; p < 4; p++) acc[s][p] = make_float2(0.f, 0.f);

#pragma unroll 2
    for (int it = 0; it < HID / 128; it++) {     // 49 iters, 128 k each
        const int q = it * 32 + lane;            // uint2 idx; k = 4q
        uint2 w0 = __ldcs(r0 + q), w1 = __ldcs(r1 + q), w2 = __ldcs(r2 + q);
        uint2 w3 = __ldcs(r3 + q), w4 = __ldcs(r4 + q), w5 = __ldcs(r5 + q);

        float2 hk[4][4];
#pragma unroll
        for (int p = 0; p < 4; p++) {
            int Ua = p * HID2 + 2 * q;
            float4 h01 = hp4[swz(Ua)];
            float4 h23 = hp4[swz(Ua + 1)];
            hk[p][0] = make_float2(h01.x, h01.y);
            hk[p][1] = make_float2(h01.z, h01.w);
            hk[p][2] = make_float2(h23.x, h23.y);
            hk[p][3] = make_float2(h23.z, h23.w);
        }

        uint2 ws[6] = {w0, w1, w2, w3, w4, w5};
#pragma unroll
        for (int s = 0; s < 6; s++) {
            float f0 = __uint_as_float(ws[s].x << 16);
            float f1 = __uint_as_float(ws[s].x & 0xFFFF0000u);
            float f2 = __uint_as_float(ws[s].y << 16);
            float f3 = __uint_as_float(ws[s].y & 0xFFFF0000u);
            float2 d0 = make_float2(f0, f0), d1 = make_float2(f1, f1);
            float2 d2 = make_float2(f2, f2), d3 = make_float2(f3, f3);
#pragma unroll
            for (int p = 0; p < 4; p++) {
                FFMA2ACC(acc[s][p], d0, hk[p][0]);
                FFMA2ACC(acc[s][p], d1, hk[p][1]);
                FFMA2ACC(acc[s][p], d2, hk[p][2]);
                FFMA2ACC(acc[s][p], d3, hk[p][3]);
            }
        }
    }
    gru_epilogue(jA,     lane, hp4, acc[0], acc[1], acc[2], bhh, t, hout);
    gru_epilogue(jA + 1, lane, hp4, acc[3], acc[4], acc[5], bhh, t, hout);
}

// stream 1 unit j (3 bf16 rows)
__device__ __forceinline__ void gru_stream1(
    int j, int lane, const float4* hp4,
    const float* __restrict__ bhh, int t, float* __restrict__ hout)
{
    const uint2* r0 = g_WBF + (size_t)j * HID4;
    const uint2* r1 = g_WBF + (size_t)(j + HID) * HID4;
    const uint2* r2 = g_WBF + (size_t)(j + 2*HID) * HID4;

    float2 acc[3][4];
#pragma unroll
    for (int s = 0; s < 3; s++)
#pragma unroll
        for (int p = 0; p < 4; p++) acc[s][p] = make_float2(0.f, 0.f);

#pragma unroll 2
    for (int it = 0; it < HID / 128; it++) {
        const int q = it * 32 + lane;
        uint2 w0 = __ldcs(r0 + q), w1 = __ldcs(r1 + q), w2 = __ldcs(r2 + q);

        float2 hk[4][4];
#pragma unroll
        for (int p = 0; p < 4; p++) {
            int Ua = p * HID2 + 2 * q;
            float4 h01 = hp4[swz(Ua)];
            float4 h23 = hp4[swz(Ua + 1)];
            hk[p][0] = make_float2(h01.x, h01.y);
            hk[p][1] = make_float2(h01.z, h01.w);
            hk[p][2] = make_float2(h23.x, h23.y);
            hk[p][3] = make_float2(h23.z, h23.w);
        }

        uint2 ws[3] = {w0, w1, w2};
#pragma unroll
        for (int s = 0; s < 3; s++) {
            float f0 = __uint_as_float(ws[s].x << 16);
            float f1 = __uint_as_float(ws[s].x & 0xFFFF0000u);
            float f2 = __uint_as_float(ws[s].y << 16);
            float f3 = __uint_as_float(ws[s].y & 0xFFFF0000u);
            float2 d0 = make_float2(f0, f0), d1 = make_float2(f1, f1);
            float2 d2 = make_float2(f2, f2), d3 = make_float2(f3, f3);
#pragma unroll
            for (int p = 0; p < 4; p++) {
                FFMA2ACC(acc[s][p], d0, hk[p][0]);
                FFMA2ACC(acc[s][p], d1, hk[p][1]);
                FFMA2ACC(acc[s][p], d2, hk[p][2]);
                FFMA2ACC(acc[s][p], d3, hk[p][3]);
            }
        }
    }
    gru_epilogue(j, lane, hp4, acc[0], acc[1], acc[2], bhh, t, hout);
}

__global__ __launch_bounds__(GRU_THREADS, 1)
void gru_step_kernel(const float* __restrict__ bhh,
                     const float* __restrict__ h0,
                     int t)
{
    extern __shared__ float4 hp4[];   // 4*HID2 swizzled units

    const float* hin  = (t == 0) ? h0 : g_H[(t + 1) & 1];
    float*       hout = g_H[t & 1];
    const int tid = threadIdx.x;

    // fill: unit U = p*HID2 + m  <-  rows 2p, 2p+1 at float2 m
    const float2* hin2 = (const float2*)hin;
    for (int u = tid; u < 4 * HID2; u += GRU_THREADS) {
        int p = u / HID2, m = u - p * HID2;
        float2 a = hin2[(size_t)(2 * p) * HID2 + m];
        float2 b = hin2[(size_t)(2 * p + 1) * HID2 + m];
        hp4[swz(u)] = make_float4(a.x, b.x, a.y, b.y);
    }
    __syncthreads();

    const int warpId = tid >> 5;
    const int lane   = tid & 31;
    const int slot   = blockIdx.x * GRU_WARPS + warpId;   // 0..2071

    gru_stream2(2 * slot, lane, hp4, bhh, t, hout);           // units 0..4143
    gru_stream1(P2_BASE + slot, lane, hp4, bhh, t, hout);     // 4144..6215
    if (slot < P3_COUNT)
        gru_stream1(P3_BASE + slot, lane, hp4, bhh, t, hout); // 6216..6271
}

// =====================================================================
// K5: samples = h @ fc2_w^T + fc2_b ; labels (int32) appended as float32.
// =====================================================================
__global__ void final_fc_kernel(const float* __restrict__ fw,
                                const float* __restrict__ fb,
                                const int* __restrict__ labels,
                                float* __restrict__ out)
{
    const float* h = g_H[(NW - 1) & 1];   // g_H[1]
    const int warpId = threadIdx.x >> 5;
    const int lane   = threadIdx.x & 31;

    for (int p = warpId; p < BB * 10; p += 8) {
        int b = p / 10, c = p % 10;
        const float* hb = h + (size_t)b * HID;
        const float* wc = fw + (size_t)c * HID;
        float s = 0.f;
        for (int k = lane; k < HID; k += 32)
            s = fmaf(hb[k], wc[k], s);
#pragma unroll
        for (int off = 16; off > 0; off >>= 1)
            s += __shfl_xor_sync(0xffffffffu, s, off);
        if (lane == 0)
            out[b * 10 + c] = s + fb[c];
    }
    if (threadIdx.x < BB)
        out[BB * 10 + threadIdx.x] = (float)labels[threadIdx.x];
}

// =====================================================================
extern "C" void kernel_launch(void* const* d_in, const int* in_sizes, int n_in,
                              void* d_out, int out_size)
{
    const float* x       = (const float*)d_in[0];
    const int*   labels  = (const int*)d_in[1];
    const float* h0      = (const float*)d_in[2];
    const float* conv1_w = (const float*)d_in[3];
    const float* conv1_b = (const float*)d_in[4];
    const float* conv2_w = (const float*)d_in[5];
    const float* conv2_b = (const float*)d_in[6];
    const float* w_ih    = (const float*)d_in[7];
    const float* w_hh    = (const float*)d_in[8];
    const float* b_ih    = (const float*)d_in[9];
    const float* b_hh    = (const float*)d_in[10];
    const float* fc2_w   = (const float*)d_in[11];
    const float* fc2_b   = (const float*)d_in[12];
    float*       out     = (float*)d_out;

    cudaFuncSetAttribute(gru_step_kernel,
                         cudaFuncAttributeMaxDynamicSharedMemorySize, GRU_SMEM);

    whh_to_bf16_kernel<<<2048, 256>>>(w_hh);
    conv1_kernel<<<dim3(P1H, WIN), dim3(41, 8)>>>(x, conv1_w, conv1_b);
    conv2_kernel<<<dim3(P2H, WIN), dim3(14, 16)>>>(conv2_w, conv2_b);
    gi_gemm_kernel<<<G3 / 128, 256>>>(w_ih, b_ih);
    for (int t = 0; t < NW; t++)
        gru_step_kernel<<<GRU_BLOCKS, GRU_THREADS, GRU_SMEM>>>(b_hh, h0, t);
    final_fc_kernel<<<1, 256>>>(fc2_w, fc2_b, labels, out);
}

// round 16
// speedup vs baseline: 1.2495x; 1.1315x over previous
#include <cuda_runtime.h>
#include <cuda_bf16.h>
#include <math.h>

// ---------------- problem constants ----------------
#define BB    8
#define FREQ  257
#define TT    1345
#define NF    128
#define NS    64
#define NW    20          // (1345-128-1)/64 + 1
#define WIN   (BB*NW)     // 160
#define C1    8
#define P1H   84
#define P1W   41
#define C2    16
#define P2H   28
#define P2W   14
#define HID   6272        // 16*28*14
#define G3    (3*HID)     // 18816
#define HID2  (HID/2)     // 3136 float2 per row
#define HID4  (HID/4)     // 1568 uint2 (bf16x4) per row

#define GRU_BLOCKS  148
#define GRU_WARPS   14
#define GRU_THREADS (GRU_WARPS*32)               // 448
#define GRU_SLOTS   (GRU_BLOCKS*GRU_WARPS)       // 2072
#define GRU_SMEM    (4*HID2*(int)sizeof(float4)) // 200704 B
#define P1_UNITS    (2*GRU_SLOTS)                // 4144
#define P2_BASE     P1_UNITS                     // 4144
#define P3_BASE     (P1_UNITS + GRU_SLOTS)       // 6216
#define P3_COUNT    (HID - P3_BASE)              // 56

// GI tf32 mma tiling (synchronous, single-buffer)
#define GI_BN   128
#define GI_BK   32
#define GI_LDF  36                   // padded ld in floats (conflict-free)
#define GI_NBLK (G3/GI_BN)           // 147
#define GI_NCHUNK (HID/GI_BK)        // 196

// packed fp32x2 FMA: acc = a*b + acc
#define FFMA2ACC(acc, a, b) asm("fma.rn.f32x2 %0, %1, %2, %0;" \
    : "+l"(*(unsigned long long*)&(acc)) \
    : "l"(*(const unsigned long long*)&(a)), "l"(*(const unsigned long long*)&(b)))

// ---------------- device scratch (no allocation allowed) ----------------
__device__ float g_P1[WIN * C1 * P1H * P1W];              // conv1 output
__device__ __align__(16) float g_FEATS[WIN * HID];        // conv2 out, tf32-rounded fp32
__device__ float g_GI[(size_t)WIN * G3];                  // GI GEMM result (no bias)
__device__ float g_H[2][BB * HID];                        // ping-pong hidden state
__device__ __align__(16) uint2 g_WBF[(size_t)G3 * HID4];  // w_hh bf16 (236 MB)

// tf32 round-to-nearest (rna)
__device__ __forceinline__ float tf32r(float x)
{
    unsigned u;
    asm("cvt.rna.tf32.f32 %0, %1;" : "=r"(u) : "f"(x));
    return __uint_as_float(u);
}

// =====================================================================
// K0: w_hh fp32 -> bf16 (device symbol referenced INSIDE kernel).
// =====================================================================
__global__ void whh_to_bf16_kernel(const float4* __restrict__ src)
{
    const size_t n4 = (size_t)G3 * HID4;
    for (size_t i = (size_t)blockIdx.x * blockDim.x + threadIdx.x;
         i < n4; i += (size_t)gridDim.x * blockDim.x) {
        float4 v = src[i];
        __nv_bfloat162 lo = __floats2bfloat162_rn(v.x, v.y);
        __nv_bfloat162 hi = __floats2bfloat162_rn(v.z, v.w);
        uint2 o;
        o.x = *(unsigned*)&lo;
        o.y = *(unsigned*)&hi;
        g_WBF[i] = o;
    }
}

// =====================================================================
// K1: conv1 (1->8ch, 9x9, pad2) + maxpool3 + leaky_relu, fused.
// =====================================================================
__global__ void conv1_kernel(const float* __restrict__ x,
                             const float* __restrict__ w,
                             const float* __restrict__ bias)
{
    __shared__ float tile[11][132];
    __shared__ float Ws[C1][9][9];

    const int pr  = blockIdx.x;
    const int win = blockIdx.y;
    const int b   = win / NW;
    const int wdx = win % NW;
    const int tid = threadIdx.y * 41 + threadIdx.x;

    for (int i = tid; i < C1 * 81; i += 328)
        ((float*)Ws)[i] = w[i];

    const float* xb = x + (size_t)b * FREQ * TT + TT + wdx * NS;
    const int r0 = 3 * pr - 2;
    for (int i = tid; i < 11 * 132; i += 328) {
        int r = i / 132, c = i % 132;
        int gr = r0 + r, gc = c - 2;
        float v = 0.f;
        if (gr >= 0 && gr < 256 && gc >= 0 && gc < NF)
            v = xb[(size_t)gr * TT + gc];
        tile[r][c] = v;
    }
    __syncthreads();

    const int ch = threadIdx.y;
    const int tc = threadIdx.x;
    const float bv = bias[ch];
    float acc[3][3];
#pragma unroll
    for (int i = 0; i < 3; i++)
#pragma unroll
        for (int j = 0; j < 3; j++) acc[i][j] = bv;

#pragma unroll
    for (int r = 0; r < 11; r++) {
        float v[11];
#pragma unroll
        for (int m = 0; m < 11; m++) v[m] = tile[r][3 * tc + m];
#pragma unroll
        for (int i = 0; i < 3; i++) {
            const int kr = r - i;
            if (kr >= 0 && kr <= 8) {
#pragma unroll
                for (int kc = 0; kc < 9; kc++) {
                    float wv = Ws[ch][kr][kc];
                    acc[i][0] = fmaf(wv, v[kc],     acc[i][0]);
                    acc[i][1] = fmaf(wv, v[kc + 1], acc[i][1]);
                    acc[i][2] = fmaf(wv, v[kc + 2], acc[i][2]);
                }
            }
        }
    }
    float m = acc[0][0];
#pragma unroll
    for (int i = 0; i < 3; i++)
#pragma unroll
        for (int j = 0; j < 3; j++) m = fmaxf(m, acc[i][j]);
    float o = (m > 0.f) ? m : 0.01f * m;
    g_P1[(((size_t)win * C1 + ch) * P1H + pr) * P1W + tc] = o;
}

// =====================================================================
// K2: conv2 (8->16ch, 4x4, pad2) + maxpool3 + leaky_relu; tf32-rounded fp32
// =====================================================================
__global__ void conv2_kernel(const float* __restrict__ w,
                             const float* __restrict__ bias)
{
    __shared__ float tile[C1][6][46];
    __shared__ float Ws[C2][C1][4][4];

    const int pr  = blockIdx.x;
    const int win = blockIdx.y;
    const int tid = threadIdx.y * 14 + threadIdx.x;

    for (int i = tid; i < C2 * C1 * 16; i += 224)
        ((float*)Ws)[i] = w[i];

    const float* src = g_P1 + (size_t)win * C1 * P1H * P1W;
    const int r0 = 3 * pr - 2;
    for (int i = tid; i < C1 * 6 * 46; i += 224) {
        int ich = i / (6 * 46);
        int rem = i % (6 * 46);
        int r = rem / 46, c = rem % 46;
        int gr = r0 + r, gc = c - 2;
        float v = 0.f;
        if (gr >= 0 && gr < P1H && gc >= 0 && gc < P1W)
            v = src[((size_t)ich * P1H + gr) * P1W + gc];
        tile[ich][r][c] = v;
    }
    __syncthreads();

    const int pc = threadIdx.x;
    const int oc = threadIdx.y;
    const float bv = bias[oc];
    float acc[3][3];
#pragma unroll
    for (int i = 0; i < 3; i++)
#pragma unroll
        for (int j = 0; j < 3; j++) acc[i][j] = bv;

#pragma unroll
    for (int ich = 0; ich < C1; ich++) {
#pragma unroll
        for (int r = 0; r < 6; r++) {
            float v[6];
#pragma unroll
            for (int m = 0; m < 6; m++) v[m] = tile[ich][r][3 * pc + m];
#pragma unroll
            for (int i = 0; i < 3; i++) {
                const int kr = r - i;
                if (kr >= 0 && kr <= 3) {
#pragma unroll
                    for (int kc = 0; kc < 4; kc++) {
                        float wv = Ws[oc][ich][kr][kc];
                        acc[i][0] = fmaf(wv, v[kc],     acc[i][0]);
                        acc[i][1] = fmaf(wv, v[kc + 1], acc[i][1]);
                        acc[i][2] = fmaf(wv, v[kc + 2], acc[i][2]);
                    }
                }
            }
        }
    }
    float m = acc[0][0];
#pragma unroll
    for (int i = 0; i < 3; i++)
#pragma unroll
        for (int j = 0; j < 3; j++) m = fmaxf(m, acc[i][j]);
    float o = (m > 0.f) ? m : 0.01f * m;
    g_FEATS[(size_t)win * HID + oc * (P2H * P2W) + pr * P2W + pc] = tf32r(o);
}

// =====================================================================
// K3: GI = FEATS(160x6272) @ w_ih^T -> fp32 via tf32 tensor cores.
// mma.sync.aligned.m16n8k8.row.col.f32.tf32.tf32.f32; plain-LDS fragments.
// BN=128 (147 blocks), BK=32, 8 warps: warp = 16-wide n-tile x 10 m-tiles.
// w_ih streamed fp32 and tf32-rounded in registers during smem fill.
// =====================================================================
__device__ __forceinline__ void mma_tf32(float& c0, float& c1, float& c2, float& c3,
                                         float a0, float a1, float a2, float a3,
                                         float b0, float b1)
{
    asm volatile("mma.sync.aligned.m16n8k8.row.col.f32.tf32.tf32.f32 "
                 "{%0,%1,%2,%3}, {%4,%5,%6,%7}, {%8,%9}, {%0,%1,%2,%3};"
                 : "+f"(c0), "+f"(c1), "+f"(c2), "+f"(c3)
                 : "r"(__float_as_uint(a0)), "r"(__float_as_uint(a1)),
                   "r"(__float_as_uint(a2)), "r"(__float_as_uint(a3)),
                   "r"(__float_as_uint(b0)), "r"(__float_as_uint(b1)));
}

__global__ __launch_bounds__(256, 1)
void gi_gemm_tf32_kernel(const float* __restrict__ wih)
{
    __shared__ __align__(16) float As[160 * GI_LDF];     // 23.0 KB
    __shared__ __align__(16) float Bs[GI_BN * GI_LDF];   // 18.4 KB

    const int tid   = threadIdx.x;
    const int warpN = tid >> 5;          // 0..7 -> 16-wide n-tile
    const int lane  = tid & 31;
    const int n0    = blockIdx.x * GI_BN;
    const int g     = lane >> 2;         // 0..7
    const int t     = lane & 3;          // 0..3

    float acc[10][2][4];
#pragma unroll
    for (int m = 0; m < 10; m++)
#pragma unroll
        for (int h = 0; h < 2; h++)
#pragma unroll
            for (int c = 0; c < 4; c++) acc[m][h][c] = 0.f;

    for (int ch = 0; ch < GI_NCHUNK; ch++) {
        const int k0 = ch * GI_BK;

        // fill As: 160 rows x 32 floats = 1280 float4 segs (already tf32-rounded)
        for (int i = tid; i < 1280; i += 256) {
            int m = i >> 3, seg = i & 7;
            float4 v = *(const float4*)(g_FEATS + (size_t)m * HID + k0 + seg * 4);
            *(float4*)(As + m * GI_LDF + seg * 4) = v;
        }
        // fill Bs: 128 rows x 32 floats = 1024 float4 segs, tf32-round in regs
        for (int i = tid; i < 1024; i += 256) {
            int n = i >> 3, seg = i & 7;
            float4 v = *(const float4*)(wih + (size_t)(n0 + n) * HID + k0 + seg * 4);
            v.x = tf32r(v.x); v.y = tf32r(v.y);
            v.z = tf32r(v.z); v.w = tf32r(v.w);
            *(float4*)(Bs + n * GI_LDF + seg * 4) = v;
        }
        __syncthreads();

#pragma unroll
        for (int ks = 0; ks < GI_BK / 8; ks++) {
            const int kb = ks * 8;
            // B fragments (col-major k8 x n8), n-halves h=0/h=1
            const float* bh0 = Bs + (warpN * 16 + g) * GI_LDF + kb + t;
            const float* bh1 = Bs + (warpN * 16 + 8 + g) * GI_LDF + kb + t;
            float b00 = bh0[0], b01 = bh0[4];
            float b10 = bh1[0], b11 = bh1[4];

#pragma unroll
            for (int m = 0; m < 10; m++) {
                const float* ar0 = As + (m * 16 + g) * GI_LDF + kb + t;
                const float* ar1 = As + (m * 16 + g + 8) * GI_LDF + kb + t;
                float a0 = ar0[0], a1 = ar1[0], a2 = ar0[4], a3 = ar1[4];
                mma_tf32(acc[m][0][0], acc[m][0][1], acc[m][0][2], acc[m][0][3],
                         a0, a1, a2, a3, b00, b01);
                mma_tf32(acc[m][1][0], acc[m][1][1], acc[m][1][2], acc[m][1][3],
                         a0, a1, a2, a3, b10, b11);
            }
        }
        __syncthreads();
    }

    // store: c0,c1 -> (row g, cols 2t,2t+1); c2,c3 -> row g+8
    const int t2 = 2 * t;
#pragma unroll
    for (int m = 0; m < 10; m++) {
#pragma unroll
        for (int h = 0; h < 2; h++) {
            int col = n0 + warpN * 16 + h * 8 + t2;
            float* d0 = g_GI + (size_t)(m * 16 + g) * G3 + col;
            float* d1 = g_GI + (size_t)(m * 16 + g + 8) * G3 + col;
            *(float2*)d0 = make_float2(acc[m][h][0], acc[m][h][1]);
            *(float2*)d1 = make_float2(acc[m][h][2], acc[m][h][3]);
        }
    }
}

// =====================================================================
// K4: GRU step with bf16 w_hh (R11/R15-proven; b_ih folded into epilogue).
// =====================================================================
__device__ __forceinline__ int swz(int u) { return u ^ ((u >> 3) & 1); }

__device__ __forceinline__ void gru_epilogue(
    int j, int lane, const float4* hp4,
    float2 aR[4], float2 aZ[4], float2 aN[4],
    const float* __restrict__ bih, const float* __restrict__ bhh,
    int t, float* __restrict__ hout)
{
    float rx[4], ry[4], zx[4], zy[4], nx[4], ny[4];
#pragma unroll
    for (int p = 0; p < 4; p++) {
        rx[p] = aR[p].x; ry[p] = aR[p].y;
        zx[p] = aZ[p].x; zy[p] = aZ[p].y;
        nx[p] = aN[p].x; ny[p] = aN[p].y;
#pragma unroll
        for (int off = 16; off > 0; off >>= 1) {
            rx[p] += __shfl_xor_sync(0xffffffffu, rx[p], off);
            ry[p] += __shfl_xor_sync(0xffffffffu, ry[p], off);
            zx[p] += __shfl_xor_sync(0xffffffffu, zx[p], off);
            zy[p] += __shfl_xor_sync(0xffffffffu, zy[p], off);
            nx[p] += __shfl_xor_sync(0xffffffffu, nx[p], off);
            ny[p] += __shfl_xor_sync(0xffffffffu, ny[p], off);
        }
    }
    if (lane < BB) {
        const int b = lane, p = b >> 1;
        const bool hi = b & 1;
        float hr = (hi ? ry[p] : rx[p]) + bhh[j];
        float hz = (hi ? zy[p] : zx[p]) + bhh[j + HID];
        float hn = (hi ? ny[p] : nx[p]) + bhh[j + 2 * HID];
        const float* gib = g_GI + (size_t)(b * NW + t) * G3;
        float ir = gib[j] + bih[j];
        float iz = gib[j + HID] + bih[j + HID];
        float in_ = gib[j + 2 * HID] + bih[j + 2 * HID];
        float r = 1.f / (1.f + expf(-(ir + hr)));
        float z = 1.f / (1.f + expf(-(iz + hz)));
        float n = tanhf(in_ + r * hn);
        int U = p * HID2 + (j >> 1);
        const float2* h2 = (const float2*)hp4;
        float2 hpair = h2[2 * swz(U) + (j & 1)];
        float ho = hi ? hpair.y : hpair.x;
        hout[(size_t)b * HID + j] = (1.f - z) * n + z * ho;
    }
}

__device__ __forceinline__ void gru_stream2(
    int jA, int lane, const float4* hp4,
    const float* __restrict__ bih, const float* __restrict__ bhh,
    int t, float* __restrict__ hout)
{
    const uint2* r0 = g_WBF + (size_t)jA * HID4;
    const uint2* r1 = g_WBF + (size_t)(jA + HID) * HID4;
    const uint2* r2 = g_WBF + (size_t)(jA + 2*HID) * HID4;
    const uint2* r3 = r0 + HID4;
    const uint2* r4 = r1 + HID4;
    const uint2* r5 = r2 + HID4;

    float2 acc[6][4];
#pragma unroll
    for (int s = 0; s < 6; s++)
#pragma unroll
        for (int p = 0; p < 4; p++) acc[s][p] = make_float2(0.f, 0.f);

#pragma unroll 2
    for (int it = 0; it < HID / 128; it++) {
        const int q = it * 32 + lane;
        uint2 w0 = __ldcs(r0 + q), w1 = __ldcs(r1 + q), w2 = __ldcs(r2 + q);
        uint2 w3 = __ldcs(r3 + q), w4 = __ldcs(r4 + q), w5 = __ldcs(r5 + q);

        float2 hk[4][4];
#pragma unroll
        for (int p = 0; p < 4; p++) {
            int Ua = p * HID2 + 2 * q;
            float4 h01 = hp4[swz(Ua)];
            float4 h23 = hp4[swz(Ua + 1)];
            hk[p][0] = make_float2(h01.x, h01.y);
            hk[p][1] = make_float2(h01.z, h01.w);
            hk[p][2] = make_float2(h23.x, h23.y);
            hk[p][3] = make_float2(h23.z, h23.w);
        }

        uint2 ws[6] = {w0, w1, w2, w3, w4, w5};
#pragma unroll
        for (int s = 0; s < 6; s++) {
            float f0 = __uint_as_float(ws[s].x << 16);
            float f1 = __uint_as_float(ws[s].x & 0xFFFF0000u);
            float f2 = __uint_as_float(ws[s].y << 16);
            float f3 = __uint_as_float(ws[s].y & 0xFFFF0000u);
            float2 d0 = make_float2(f0, f0), d1 = make_float2(f1, f1);
            float2 d2 = make_float2(f2, f2), d3 = make_float2(f3, f3);
#pragma unroll
            for (int p = 0; p < 4; p++) {
                FFMA2ACC(acc[s][p], d0, hk[p][0]);
                FFMA2ACC(acc[s][p], d1, hk[p][1]);
                FFMA2ACC(acc[s][p], d2, hk[p][2]);
                FFMA2ACC(acc[s][p], d3, hk[p][3]);
            }
        }
    }
    gru_epilogue(jA,     lane, hp4, acc[0], acc[1], acc[2], bih, bhh, t, hout);
    gru_epilogue(jA + 1, lane, hp4, acc[3], acc[4], acc[5], bih, bhh, t, hout);
}

__device__ __forceinline__ void gru_stream1(
    int j, int lane, const float4* hp4,
    const float* __restrict__ bih, const float* __restrict__ bhh,
    int t, float* __restrict__ hout)
{
    const uint2* r0 = g_WBF + (size_t)j * HID4;
    const uint2* r1 = g_WBF + (size_t)(j + HID) * HID4;
    const uint2* r2 = g_WBF + (size_t)(j + 2*HID) * HID4;

    float2 acc[3][4];
#pragma unroll
    for (int s = 0; s < 3; s++)
#pragma unroll
        for (int p = 0; p < 4; p++) acc[s][p] = make_float2(0.f, 0.f);

#pragma unroll 2
    for (int it = 0; it < HID / 128; it++) {
        const int q = it * 32 + lane;
        uint2 w0 = __ldcs(r0 + q), w1 = __ldcs(r1 + q), w2 = __ldcs(r2 + q);

        float2 hk[4][4];
#pragma unroll
        for (int p = 0; p < 4; p++) {
            int Ua = p * HID2 + 2 * q;
            float4 h01 = hp4[swz(Ua)];
            float4 h23 = hp4[swz(Ua + 1)];
            hk[p][0] = make_float2(h01.x, h01.y);
            hk[p][1] = make_float2(h01.z, h01.w);
            hk[p][2] = make_float2(h23.x, h23.y);
            hk[p][3] = make_float2(h23.z, h23.w);
        }

        uint2 ws[3] = {w0, w1, w2};
#pragma unroll
        for (int s = 0; s < 3; s++) {
            float f0 = __uint_as_float(ws[s].x << 16);
            float f1 = __uint_as_float(ws[s].x & 0xFFFF0000u);
            float f2 = __uint_as_float(ws[s].y << 16);
            float f3 = __uint_as_float(ws[s].y & 0xFFFF0000u);
            float2 d0 = make_float2(f0, f0), d1 = make_float2(f1, f1);
            float2 d2 = make_float2(f2, f2), d3 = make_float2(f3, f3);
#pragma unroll
            for (int p = 0; p < 4; p++) {
                FFMA2ACC(acc[s][p], d0, hk[p][0]);
                FFMA2ACC(acc[s][p], d1, hk[p][1]);
                FFMA2ACC(acc[s][p], d2, hk[p][2]);
                FFMA2ACC(acc[s][p], d3, hk[p][3]);
            }
        }
    }
    gru_epilogue(j, lane, hp4, acc[0], acc[1], acc[2], bih, bhh, t, hout);
}

__global__ __launch_bounds__(GRU_THREADS, 1)
void gru_step_kernel(const float* __restrict__ bih,
                     const float* __restrict__ bhh,
                     const float* __restrict__ h0,
                     int t)
{
    extern __shared__ float4 hp4[];

    const float* hin  = (t == 0) ? h0 : g_H[(t + 1) & 1];
    float*       hout = g_H[t & 1];
    const int tid = threadIdx.x;

    const float2* hin2 = (const float2*)hin;
    for (int u = tid; u < 4 * HID2; u += GRU_THREADS) {
        int p = u / HID2, m = u - p * HID2;
        float2 a = hin2[(size_t)(2 * p) * HID2 + m];
        float2 b = hin2[(size_t)(2 * p + 1) * HID2 + m];
        hp4[swz(u)] = make_float4(a.x, b.x, a.y, b.y);
    }
    __syncthreads();

    const int warpId = tid >> 5;
    const int lane   = tid & 31;
    const int slot   = blockIdx.x * GRU_WARPS + warpId;

    gru_stream2(2 * slot, lane, hp4, bih, bhh, t, hout);
    gru_stream1(P2_BASE + slot, lane, hp4, bih, bhh, t, hout);
    if (slot < P3_COUNT)
        gru_stream1(P3_BASE + slot, lane, hp4, bih, bhh, t, hout);
}

// =====================================================================
// K5: samples = h @ fc2_w^T + fc2_b ; labels (int32) appended as float32.
// =====================================================================
__global__ void final_fc_kernel(const float* __restrict__ fw,
                                const float* __restrict__ fb,
                                const int* __restrict__ labels,
                                float* __restrict__ out)
{
    const float* h = g_H[(NW - 1) & 1];   // g_H[1]
    const int warpId = threadIdx.x >> 5;
    const int lane   = threadIdx.x & 31;

    for (int p = warpId; p < BB * 10; p += 8) {
        int b = p / 10, c = p % 10;
        const float* hb = h + (size_t)b * HID;
        const float* wc = fw + (size_t)c * HID;
        float s = 0.f;
        for (int k = lane; k < HID; k += 32)
            s = fmaf(hb[k], wc[k], s);
#pragma unroll
        for (int off = 16; off > 0; off >>= 1)
            s += __shfl_xor_sync(0xffffffffu, s, off);
        if (lane == 0)
            out[b * 10 + c] = s + fb[c];
    }
    if (threadIdx.x < BB)
        out[BB * 10 + threadIdx.x] = (float)labels[threadIdx.x];
}

// =====================================================================
extern "C" void kernel_launch(void* const* d_in, const int* in_sizes, int n_in,
                              void* d_out, int out_size)
{
    const float* x       = (const float*)d_in[0];
    const int*   labels  = (const int*)d_in[1];
    const float* h0      = (const float*)d_in[2];
    const float* conv1_w = (const float*)d_in[3];
    const float* conv1_b = (const float*)d_in[4];
    const float* conv2_w = (const float*)d_in[5];
    const float* conv2_b = (const float*)d_in[6];
    const float* w_ih    = (const float*)d_in[7];
    const float* w_hh    = (const float*)d_in[8];
    const float* b_ih    = (const float*)d_in[9];
    const float* b_hh    = (const float*)d_in[10];
    const float* fc2_w   = (const float*)d_in[11];
    const float* fc2_b   = (const float*)d_in[12];
    float*       out     = (float*)d_out;

    cudaFuncSetAttribute(gru_step_kernel,
                         cudaFuncAttributeMaxDynamicSharedMemorySize, GRU_SMEM);

    whh_to_bf16_kernel<<<2048, 256>>>((const float4*)w_hh);
    conv1_kernel<<<dim3(P1H, WIN), dim3(41, 8)>>>(x, conv1_w, conv1_b);
    conv2_kernel<<<dim3(P2H, WIN), dim3(14, 16)>>>(conv2_w, conv2_b);
    gi_gemm_tf32_kernel<<<GI_NBLK, 256>>>(w_ih);
    for (int t = 0; t < NW; t++)
        gru_step_kernel<<<GRU_BLOCKS, GRU_THREADS, GRU_SMEM>>>(b_ih, b_hh, h0, t);
    final_fc_kernel<<<1, 256>>>(fc2_w, fc2_b, labels, out);
}

// round 17
// speedup vs baseline: 1.6134x; 1.2912x over previous
#include <cuda_runtime.h>
#include <cuda_bf16.h>
#include <math.h>

// ---------------- problem constants ----------------
#define BB    8
#define FREQ  257
#define TT    1345
#define NF    128
#define NS    64
#define NW    20          // (1345-128-1)/64 + 1
#define WIN   (BB*NW)     // 160
#define C1    8
#define P1H   84
#define P1W   41
#define C2    16
#define P2H   28
#define P2W   14
#define HID   6272        // 16*28*14
#define G3    (3*HID)     // 18816
#define HID2  (HID/2)     // 3136 float2 per row
#define HID4  (HID/4)     // 1568 uint2 (bf16x4) per row

#define GRU_BLOCKS  148
#define GRU_WARPS   14
#define GRU_THREADS (GRU_WARPS*32)               // 448
#define GRU_SLOTS   (GRU_BLOCKS*GRU_WARPS)       // 2072
#define GRU_SMEM    (4*HID2*(int)sizeof(float4)) // 200704 B
#define P1_UNITS    (2*GRU_SLOTS)                // 4144
#define P2_BASE     P1_UNITS                     // 4144
#define P3_BASE     (P1_UNITS + GRU_SLOTS)       // 6216
#define P3_COUNT    (HID - P3_BASE)              // 56

// GI tf32 mma tiling: BN=64, 294 blocks (2/SM), cp.async double-buffered
#define GI_BN   64
#define GI_BK   32
#define GI_LDF  36                    // padded ld in floats (conflict-free)
#define GI_NBLK (G3/GI_BN)            // 294
#define GI_NCHUNK (HID/GI_BK)         // 196
#define GI_AS_FLOATS (160*GI_LDF)     // 5760
#define GI_BS_FLOATS (GI_BN*GI_LDF)   // 2304
#define GI_BUF_FLOATS (GI_AS_FLOATS + GI_BS_FLOATS)   // 8064
#define GI_SMEM (2*GI_BUF_FLOATS*(int)sizeof(float))  // 64512 B

// packed fp32x2 FMA: acc = a*b + acc
#define FFMA2ACC(acc, a, b) asm("fma.rn.f32x2 %0, %1, %2, %0;" \
    : "+l"(*(unsigned long long*)&(acc)) \
    : "l"(*(const unsigned long long*)&(a)), "l"(*(const unsigned long long*)&(b)))

#define CP_ASYNC16(smem_u32, gptr) \
    asm volatile("cp.async.cg.shared.global [%0], [%1], 16;\n" :: "r"(smem_u32), "l"(gptr))
#define CP_COMMIT() asm volatile("cp.async.commit_group;\n" ::: "memory")
#define CP_WAIT1()  asm volatile("cp.async.wait_group 1;\n" ::: "memory")
#define CP_WAIT0()  asm volatile("cp.async.wait_group 0;\n" ::: "memory")

// ---------------- device scratch (no allocation allowed) ----------------
__device__ float g_P1[WIN * C1 * P1H * P1W];              // conv1 output
__device__ __align__(16) float g_FEATS[WIN * HID];        // conv2 out, tf32-rounded fp32
__device__ float g_GI[(size_t)WIN * G3];                  // GI GEMM result (no bias)
__device__ float g_H[2][BB * HID];                        // ping-pong hidden state
__device__ __align__(16) uint2 g_WBF[(size_t)G3 * HID4];  // w_hh bf16 (236 MB)

// tf32 round-to-nearest (rna)
__device__ __forceinline__ float tf32r(float x)
{
    unsigned u;
    asm("cvt.rna.tf32.f32 %0, %1;" : "=r"(u) : "f"(x));
    return __uint_as_float(u);
}

// =====================================================================
// K0: w_hh fp32 -> bf16 (device symbol referenced INSIDE kernel).
// =====================================================================
__global__ void whh_to_bf16_kernel(const float4* __restrict__ src)
{
    const size_t n4 = (size_t)G3 * HID4;
    for (size_t i = (size_t)blockIdx.x * blockDim.x + threadIdx.x;
         i < n4; i += (size_t)gridDim.x * blockDim.x) {
        float4 v = src[i];
        __nv_bfloat162 lo = __floats2bfloat162_rn(v.x, v.y);
        __nv_bfloat162 hi = __floats2bfloat162_rn(v.z, v.w);
        uint2 o;
        o.x = *(unsigned*)&lo;
        o.y = *(unsigned*)&hi;
        g_WBF[i] = o;
    }
}

// =====================================================================
// K1: conv1 (1->8ch, 9x9, pad2) + maxpool3 + leaky_relu, fused.
// =====================================================================
__global__ void conv1_kernel(const float* __restrict__ x,
                             const float* __restrict__ w,
                             const float* __restrict__ bias)
{
    __shared__ float tile[11][132];
    __shared__ float Ws[C1][9][9];

    const int pr  = blockIdx.x;
    const int win = blockIdx.y;
    const int b   = win / NW;
    const int wdx = win % NW;
    const int tid = threadIdx.y * 41 + threadIdx.x;

    for (int i = tid; i < C1 * 81; i += 328)
        ((float*)Ws)[i] = w[i];

    const float* xb = x + (size_t)b * FREQ * TT + TT + wdx * NS;
    const int r0 = 3 * pr - 2;
    for (int i = tid; i < 11 * 132; i += 328) {
        int r = i / 132, c = i % 132;
        int gr = r0 + r, gc = c - 2;
        float v = 0.f;
        if (gr >= 0 && gr < 256 && gc >= 0 && gc < NF)
            v = xb[(size_t)gr * TT + gc];
        tile[r][c] = v;
    }
    __syncthreads();

    const int ch = threadIdx.y;
    const int tc = threadIdx.x;
    const float bv = bias[ch];
    float acc[3][3];
#pragma unroll
    for (int i = 0; i < 3; i++)
#pragma unroll
        for (int j = 0; j < 3; j++) acc[i][j] = bv;

#pragma unroll
    for (int r = 0; r < 11; r++) {
        float v[11];
#pragma unroll
        for (int m = 0; m < 11; m++) v[m] = tile[r][3 * tc + m];
#pragma unroll
        for (int i = 0; i < 3; i++) {
            const int kr = r - i;
            if (kr >= 0 && kr <= 8) {
#pragma unroll
                for (int kc = 0; kc < 9; kc++) {
                    float wv = Ws[ch][kr][kc];
                    acc[i][0] = fmaf(wv, v[kc],     acc[i][0]);
                    acc[i][1] = fmaf(wv, v[kc + 1], acc[i][1]);
                    acc[i][2] = fmaf(wv, v[kc + 2], acc[i][2]);
                }
            }
        }
    }
    float m = acc[0][0];
#pragma unroll
    for (int i = 0; i < 3; i++)
#pragma unroll
        for (int j = 0; j < 3; j++) m = fmaxf(m, acc[i][j]);
    float o = (m > 0.f) ? m : 0.01f * m;
    g_P1[(((size_t)win * C1 + ch) * P1H + pr) * P1W + tc] = o;
}

// =====================================================================
// K2: conv2 (8->16ch, 4x4, pad2) + maxpool3 + leaky_relu; tf32-rounded fp32
// =====================================================================
__global__ void conv2_kernel(const float* __restrict__ w,
                             const float* __restrict__ bias)
{
    __shared__ float tile[C1][6][46];
    __shared__ float Ws[C2][C1][4][4];

    const int pr  = blockIdx.x;
    const int win = blockIdx.y;
    const int tid = threadIdx.y * 14 + threadIdx.x;

    for (int i = tid; i < C2 * C1 * 16; i += 224)
        ((float*)Ws)[i] = w[i];

    const float* src = g_P1 + (size_t)win * C1 * P1H * P1W;
    const int r0 = 3 * pr - 2;
    for (int i = tid; i < C1 * 6 * 46; i += 224) {
        int ich = i / (6 * 46);
        int rem = i % (6 * 46);
        int r = rem / 46, c = rem % 46;
        int gr = r0 + r, gc = c - 2;
        float v = 0.f;
        if (gr >= 0 && gr < P1H && gc >= 0 && gc < P1W)
            v = src[((size_t)ich * P1H + gr) * P1W + gc];
        tile[ich][r][c] = v;
    }
    __syncthreads();

    const int pc = threadIdx.x;
    const int oc = threadIdx.y;
    const float bv = bias[oc];
    float acc[3][3];
#pragma unroll
    for (int i = 0; i < 3; i++)
#pragma unroll
        for (int j = 0; j < 3; j++) acc[i][j] = bv;

#pragma unroll
    for (int ich = 0; ich < C1; ich++) {
#pragma unroll
        for (int r = 0; r < 6; r++) {
            float v[6];
#pragma unroll
            for (int m = 0; m < 6; m++) v[m] = tile[ich][r][3 * pc + m];
#pragma unroll
            for (int i = 0; i < 3; i++) {
                const int kr = r - i;
                if (kr >= 0 && kr <= 3) {
#pragma unroll
                    for (int kc = 0; kc < 4; kc++) {
                        float wv = Ws[oc][ich][kr][kc];
                        acc[i][0] = fmaf(wv, v[kc],     acc[i][0]);
                        acc[i][1] = fmaf(wv, v[kc + 1], acc[i][1]);
                        acc[i][2] = fmaf(wv, v[kc + 2], acc[i][2]);
                    }
                }
            }
        }
    }
    float m = acc[0][0];
#pragma unroll
    for (int i = 0; i < 3; i++)
#pragma unroll
        for (int j = 0; j < 3; j++) m = fmaxf(m, acc[i][j]);
    float o = (m > 0.f) ? m : 0.01f * m;
    g_FEATS[(size_t)win * HID + oc * (P2H * P2W) + pr * P2W + pc] = tf32r(o);
}

// =====================================================================
// K3: GI = FEATS(160x6272) @ w_ih^T -> fp32 via tf32 mma m16n8k8.
// cp.async double-buffered, BN=64, 294 blocks (2/SM), 8 warps =
// 4 n-tiles x 2 m-groups (5 m-tiles each). Fragment maps = R16-proven.
// Bs streamed raw fp32 (HW tf32 truncation); As pre-rounded (rna) by conv2.
// =====================================================================
__device__ __forceinline__ void mma_tf32(float& c0, float& c1, float& c2, float& c3,
                                         float a0, float a1, float a2, float a3,
                                         float b0, float b1)
{
    asm volatile("mma.sync.aligned.m16n8k8.row.col.f32.tf32.tf32.f32 "
                 "{%0,%1,%2,%3}, {%4,%5,%6,%7}, {%8,%9}, {%0,%1,%2,%3};"
                 : "+f"(c0), "+f"(c1), "+f"(c2), "+f"(c3)
                 : "r"(__float_as_uint(a0)), "r"(__float_as_uint(a1)),
                   "r"(__float_as_uint(a2)), "r"(__float_as_uint(a3)),
                   "r"(__float_as_uint(b0)), "r"(__float_as_uint(b1)));
}

__global__ __launch_bounds__(256, 2)
void gi_gemm_tf32_kernel(const float* __restrict__ wih)
{
    extern __shared__ __align__(16) float gis[];   // 2 x (As 5760 + Bs 2304)

    const int tid   = threadIdx.x;
    const int wid   = tid >> 5;
    const int warpN = wid & 3;           // 0..3 -> 16-wide n-tile
    const int warpM = wid >> 2;          // 0..1 -> 5 m-tiles
    const int lane  = tid & 31;
    const int n0    = blockIdx.x * GI_BN;
    const int g     = lane >> 2;         // 0..7
    const int t     = lane & 3;          // 0..3

    float acc[5][2][4];
#pragma unroll
    for (int m = 0; m < 5; m++)
#pragma unroll
        for (int h = 0; h < 2; h++)
#pragma unroll
            for (int c = 0; c < 4; c++) acc[m][h][c] = 0.f;

    // issue cp.async fills for chunk c into buffer (c&1)
    auto issue = [&](int c) {
        const int k0 = c * GI_BK;
        float* As = gis + (c & 1) * GI_BUF_FLOATS;
        float* Bs = As + GI_AS_FLOATS;
        // As: 160 rows x 8 float4 segs = 1280
        for (int i = tid; i < 1280; i += 256) {
            int m = i >> 3, seg = i & 7;
            unsigned d = (unsigned)__cvta_generic_to_shared(As + m * GI_LDF + seg * 4);
            CP_ASYNC16(d, g_FEATS + (size_t)m * HID + k0 + seg * 4);
        }
        // Bs: 64 rows x 8 segs = 512
        for (int i = tid; i < 512; i += 256) {
            int n = i >> 3, seg = i & 7;
            unsigned d = (unsigned)__cvta_generic_to_shared(Bs + n * GI_LDF + seg * 4);
            CP_ASYNC16(d, wih + (size_t)(n0 + n) * HID + k0 + seg * 4);
        }
        CP_COMMIT();
    };

    issue(0);

    for (int c = 0; c < GI_NCHUNK; c++) {
        if (c + 1 < GI_NCHUNK) { issue(c + 1); CP_WAIT1(); }
        else                   { CP_WAIT0(); }
        __syncthreads();

        const float* As = gis + (c & 1) * GI_BUF_FLOATS;
        const float* Bs = As + GI_AS_FLOATS;

#pragma unroll
        for (int ks = 0; ks < GI_BK / 8; ks++) {
            const int kb = ks * 8;
            const float* bh0 = Bs + (warpN * 16 + g) * GI_LDF + kb + t;
            const float* bh1 = Bs + (warpN * 16 + 8 + g) * GI_LDF + kb + t;
            float b00 = bh0[0], b01 = bh0[4];
            float b10 = bh1[0], b11 = bh1[4];

#pragma unroll
            for (int mi = 0; mi < 5; mi++) {
                const int m = warpM * 5 + mi;
                const float* ar0 = As + (m * 16 + g) * GI_LDF + kb + t;
                const float* ar1 = As + (m * 16 + g + 8) * GI_LDF + kb + t;
                float a0 = ar0[0], a1 = ar1[0], a2 = ar0[4], a3 = ar1[4];
                mma_tf32(acc[mi][0][0], acc[mi][0][1], acc[mi][0][2], acc[mi][0][3],
                         a0, a1, a2, a3, b00, b01);
                mma_tf32(acc[mi][1][0], acc[mi][1][1], acc[mi][1][2], acc[mi][1][3],
                         a0, a1, a2, a3, b10, b11);
            }
        }
        __syncthreads();   // all warps done with buffer (c&1) before it refills at c+2
    }

    // store: c0,c1 -> (row g, cols 2t,2t+1); c2,c3 -> row g+8
    const int t2 = 2 * t;
#pragma unroll
    for (int mi = 0; mi < 5; mi++) {
        const int m = warpM * 5 + mi;
#pragma unroll
        for (int h = 0; h < 2; h++) {
            int col = n0 + warpN * 16 + h * 8 + t2;
            float* d0 = g_GI + (size_t)(m * 16 + g) * G3 + col;
            float* d1 = g_GI + (size_t)(m * 16 + g + 8) * G3 + col;
            *(float2*)d0 = make_float2(acc[mi][h][0], acc[mi][h][1]);
            *(float2*)d1 = make_float2(acc[mi][h][2], acc[mi][h][3]);
        }
    }
}

// =====================================================================
// K4: GRU step with bf16 w_hh (R11/R16-proven; b_ih folded into epilogue).
// =====================================================================
__device__ __forceinline__ int swz(int u) { return u ^ ((u >> 3) & 1); }

__device__ __forceinline__ void gru_epilogue(
    int j, int lane, const float4* hp4,
    float2 aR[4], float2 aZ[4], float2 aN[4],
    const float* __restrict__ bih, const float* __restrict__ bhh,
    int t, float* __restrict__ hout)
{
    float rx[4], ry[4], zx[4], zy[4], nx[4], ny[4];
#pragma unroll
    for (int p = 0; p < 4; p++) {
        rx[p] = aR[p].x; ry[p] = aR[p].y;
        zx[p] = aZ[p].x; zy[p] = aZ[p].y;
        nx[p] = aN[p].x; ny[p] = aN[p].y;
#pragma unroll
        for (int off = 16; off > 0; off >>= 1) {
            rx[p] += __shfl_xor_sync(0xffffffffu, rx[p], off);
            ry[p] += __shfl_xor_sync(0xffffffffu, ry[p], off);
            zx[p] += __shfl_xor_sync(0xffffffffu, zx[p], off);
            zy[p] += __shfl_xor_sync(0xffffffffu, zy[p], off);
            nx[p] += __shfl_xor_sync(0xffffffffu, nx[p], off);
            ny[p] += __shfl_xor_sync(0xffffffffu, ny[p], off);
        }
    }
    if (lane < BB) {
        const int b = lane, p = b >> 1;
        const bool hi = b & 1;
        float hr = (hi ? ry[p] : rx[p]) + bhh[j];
        float hz = (hi ? zy[p] : zx[p]) + bhh[j + HID];
        float hn = (hi ? ny[p] : nx[p]) + bhh[j + 2 * HID];
        const float* gib = g_GI + (size_t)(b * NW + t) * G3;
        float ir = gib[j] + bih[j];
        float iz = gib[j + HID] + bih[j + HID];
        float in_ = gib[j + 2 * HID] + bih[j + 2 * HID];
        float r = 1.f / (1.f + expf(-(ir + hr)));
        float z = 1.f / (1.f + expf(-(iz + hz)));
        float n = tanhf(in_ + r * hn);
        int U = p * HID2 + (j >> 1);
        const float2* h2 = (const float2*)hp4;
        float2 hpair = h2[2 * swz(U) + (j & 1)];
        float ho = hi ? hpair.y : hpair.x;
        hout[(size_t)b * HID + j] = (1.f - z) * n + z * ho;
    }
}

__device__ __forceinline__ void gru_stream2(
    int jA, int lane, const float4* hp4,
    const float* __restrict__ bih, const float* __restrict__ bhh,
    int t, float* __restrict__ hout)
{
    const uint2* r0 = g_WBF + (size_t)jA * HID4;
    const uint2* r1 = g_WBF + (size_t)(jA + HID) * HID4;
    const uint2* r2 = g_WBF + (size_t)(jA + 2*HID) * HID4;
    const uint2* r3 = r0 + HID4;
    const uint2* r4 = r1 + HID4;
    const uint2* r5 = r2 + HID4;

    float2 acc[6][4];
#pragma unroll
    for (int s = 0; s < 6; s++)
#pragma unroll
        for (int p = 0; p < 4; p++) acc[s][p] = make_float2(0.f, 0.f);

#pragma unroll 2
    for (int it = 0; it < HID / 128; it++) {
        const int q = it * 32 + lane;
        uint2 w0 = __ldcs(r0 + q), w1 = __ldcs(r1 + q), w2 = __ldcs(r2 + q);
        uint2 w3 = __ldcs(r3 + q), w4 = __ldcs(r4 + q), w5 = __ldcs(r5 + q);

        float2 hk[4][4];
#pragma unroll
        for (int p = 0; p < 4; p++) {
            int Ua = p * HID2 + 2 * q;
            float4 h01 = hp4[swz(Ua)];
            float4 h23 = hp4[swz(Ua + 1)];
            hk[p][0] = make_float2(h01.x, h01.y);
            hk[p][1] = make_float2(h01.z, h01.w);
            hk[p][2] = make_float2(h23.x, h23.y);
            hk[p][3] = make_float2(h23.z, h23.w);
        }

        uint2 ws[6] = {w0, w1, w2, w3, w4, w5};
#pragma unroll
        for (int s = 0; s < 6; s++) {
            float f0 = __uint_as_float(ws[s].x << 16);
            float f1 = __uint_as_float(ws[s].x & 0xFFFF0000u);
            float f2 = __uint_as_float(ws[s].y << 16);
            float f3 = __uint_as_float(ws[s].y & 0xFFFF0000u);
            float2 d0 = make_float2(f0, f0), d1 = make_float2(f1, f1);
            float2 d2 = make_float2(f2, f2), d3 = make_float2(f3, f3);
#pragma unroll
            for (int p = 0; p < 4; p++) {
                FFMA2ACC(acc[s][p], d0, hk[p][0]);
                FFMA2ACC(acc[s][p], d1, hk[p][1]);
                FFMA2ACC(acc[s][p], d2, hk[p][2]);
                FFMA2ACC(acc[s][p], d3, hk[p][3]);
            }
        }
    }
    gru_epilogue(jA,     lane, hp4, acc[0], acc[1], acc[2], bih, bhh, t, hout);
    gru_epilogue(jA + 1, lane, hp4, acc[3], acc[4], acc[5], bih, bhh, t, hout);
}

__device__ __forceinline__ void gru_stream1(
    int j, int lane, const float4* hp4,
    const float* __restrict__ bih, const float* __restrict__ bhh,
    int t, float* __restrict__ hout)
{
    const uint2* r0 = g_WBF + (size_t)j * HID4;
    const uint2* r1 = g_WBF + (size_t)(j + HID) * HID4;
    const uint2* r2 = g_WBF + (size_t)(j + 2*HID) * HID4;

    float2 acc[3][4];
#pragma unroll
    for (int s = 0; s < 3; s++)
#pragma unroll
        for (int p = 0; p < 4; p++) acc[s][p] = make_float2(0.f, 0.f);

#pragma unroll 2
    for (int it = 0; it < HID / 128; it++) {
        const int q = it * 32 + lane;
        uint2 w0 = __ldcs(r0 + q), w1 = __ldcs(r1 + q), w2 = __ldcs(r2 + q);

        float2 hk[4][4];
#pragma unroll
        for (int p = 0; p < 4; p++) {
            int Ua = p * HID2 + 2 * q;
            float4 h01 = hp4[swz(Ua)];
            float4 h23 = hp4[swz(Ua + 1)];
            hk[p][0] = make_float2(h01.x, h01.y);
            hk[p][1] = make_float2(h01.z, h01.w);
            hk[p][2] = make_float2(h23.x, h23.y);
            hk[p][3] = make_float2(h23.z, h23.w);
        }

        uint2 ws[3] = {w0, w1, w2};
#pragma unroll
        for (int s = 0; s < 3; s++) {
            float f0 = __uint_as_float(ws[s].x << 16);
            float f1 = __uint_as_float(ws[s].x & 0xFFFF0000u);
            float f2 = __uint_as_float(ws[s].y << 16);
            float f3 = __uint_as_float(ws[s].y & 0xFFFF0000u);
            float2 d0 = make_float2(f0, f0), d1 = make_float2(f1, f1);
            float2 d2 = make_float2(f2, f2), d3 = make_float2(f3, f3);
#pragma unroll
            for (int p = 0; p < 4; p++) {
                FFMA2ACC(acc[s][p], d0, hk[p][0]);
                FFMA2ACC(acc[s][p], d1, hk[p][1]);
                FFMA2ACC(acc[s][p], d2, hk[p][2]);
                FFMA2ACC(acc[s][p], d3, hk[p][3]);
            }
        }
    }
    gru_epilogue(j, lane, hp4, acc[0], acc[1], acc[2], bih, bhh, t, hout);
}

__global__ __launch_bounds__(GRU_THREADS, 1)
void gru_step_kernel(const float* __restrict__ bih,
                     const float* __restrict__ bhh,
                     const float* __restrict__ h0,
                     int t)
{
    extern __shared__ float4 hp4[];

    const float* hin  = (t == 0) ? h0 : g_H[(t + 1) & 1];
    float*       hout = g_H[t & 1];
    const int tid = threadIdx.x;

    const float2* hin2 = (const float2*)hin;
    for (int u = tid; u < 4 * HID2; u += GRU_THREADS) {
        int p = u / HID2, m = u - p * HID2;
        float2 a = hin2[(size_t)(2 * p) * HID2 + m];
        float2 b = hin2[(size_t)(2 * p + 1) * HID2 + m];
        hp4[swz(u)] = make_float4(a.x, b.x, a.y, b.y);
    }
    __syncthreads();

    const int warpId = tid >> 5;
    const int lane   = tid & 31;
    const int slot   = blockIdx.x * GRU_WARPS + warpId;

    gru_stream2(2 * slot, lane, hp4, bih, bhh, t, hout);
    gru_stream1(P2_BASE + slot, lane, hp4, bih, bhh, t, hout);
    if (slot < P3_COUNT)
        gru_stream1(P3_BASE + slot, lane, hp4, bih, bhh, t, hout);
}

// =====================================================================
// K5: samples = h @ fc2_w^T + fc2_b ; labels (int32) appended as float32.
// =====================================================================
__global__ void final_fc_kernel(const float* __restrict__ fw,
                                const float* __restrict__ fb,
                                const int* __restrict__ labels,
                                float* __restrict__ out)
{
    const float* h = g_H[(NW - 1) & 1];   // g_H[1]
    const int warpId = threadIdx.x >> 5;
    const int lane   = threadIdx.x & 31;

    for (int p = warpId; p < BB * 10; p += 8) {
        int b = p / 10, c = p % 10;
        const float* hb = h + (size_t)b * HID;
        const float* wc = fw + (size_t)c * HID;
        float s = 0.f;
        for (int k = lane; k < HID; k += 32)
            s = fmaf(hb[k], wc[k], s);
#pragma unroll
        for (int off = 16; off > 0; off >>= 1)
            s += __shfl_xor_sync(0xffffffffu, s, off);
        if (lane == 0)
            out[b * 10 + c] = s + fb[c];
    }
    if (threadIdx.x < BB)
        out[BB * 10 + threadIdx.x] = (float)labels[threadIdx.x];
}

// =====================================================================
extern "C" void kernel_launch(void* const* d_in, const int* in_sizes, int n_in,
                              void* d_out, int out_size)
{
    const float* x       = (const float*)d_in[0];
    const int*   labels  = (const int*)d_in[1];
    const float* h0      = (const float*)d_in[2];
    const float* conv1_w = (const float*)d_in[3];
    const float* conv1_b = (const float*)d_in[4];
    const float* conv2_w = (const float*)d_in[5];
    const float* conv2_b = (const float*)d_in[6];
    const float* w_ih    = (const float*)d_in[7];
    const float* w_hh    = (const float*)d_in[8];
    const float* b_ih    = (const float*)d_in[9];
    const float* b_hh    = (const float*)d_in[10];
    const float* fc2_w   = (const float*)d_in[11];
    const float* fc2_b   = (const float*)d_in[12];
    float*       out     = (float*)d_out;

    cudaFuncSetAttribute(gru_step_kernel,
                         cudaFuncAttributeMaxDynamicSharedMemorySize, GRU_SMEM);
    cudaFuncSetAttribute(gi_gemm_tf32_kernel,
                         cudaFuncAttributeMaxDynamicSharedMemorySize, GI_SMEM);

    whh_to_bf16_kernel<<<2048, 256>>>((const float4*)w_hh);
    conv1_kernel<<<dim3(P1H, WIN), dim3(41, 8)>>>(x, conv1_w, conv1_b);
    conv2_kernel<<<dim3(P2H, WIN), dim3(14, 16)>>>(conv2_w, conv2_b);
    gi_gemm_tf32_kernel<<<GI_NBLK, 256, GI_SMEM>>>(w_ih);
    for (int t = 0; t < NW; t++)
        gru_step_kernel<<<GRU_BLOCKS, GRU_THREADS, GRU_SMEM>>>(b_ih, b_hh, h0, t);
    final_fc_kernel<<<1, 256>>>(fc2_w, fc2_b, labels, out);
}